// round 1
// baseline (speedup 1.0000x reference)
#include <cuda_runtime.h>

#define BATCH 64
#define NX    512
#define NY    512
#define NHEAD 8
#define DHEAD 10
#define DMODEL 80     // NHEAD*DHEAD
#define KX    768
#define KY    283

typedef unsigned long long u64;

// scratch for K/V projections (10.5 MB each) — device globals per harness rules
__device__ float g_k[BATCH * NY * DMODEL];
__device__ float g_v[BATCH * NY * DMODEL];

// ---------------- packed f32x2 helpers ----------------
__device__ __forceinline__ u64 pack2(float lo, float hi) {
    u64 r; asm("mov.b64 %0, {%1, %2};" : "=l"(r) : "f"(lo), "f"(hi)); return r;
}
__device__ __forceinline__ void unpack2(u64 v, float& lo, float& hi) {
    asm("mov.b64 {%0, %1}, %2;" : "=f"(lo), "=f"(hi) : "l"(v));
}
__device__ __forceinline__ u64 ffma2(u64 a, u64 b, u64 c) {
    u64 d; asm("fma.rn.f32x2 %0, %1, %2, %3;" : "=l"(d) : "l"(a), "l"(b), "l"(c)); return d;
}

// ---------------- Kernel A: Q projection (x @ Wq -> d_out) ----------------
// GEMM M=32768, N=80, K=768.  Block: 64 rows x 80 cols. 256 threads.
// ty = tid>>3 (0..31, 2 rows each), tx = tid&7 (10 cols each, as 5 float2).
__global__ void __launch_bounds__(256) qproj_kernel(
    const float* __restrict__ x, const float* __restrict__ Wq, float* __restrict__ out)
{
    __shared__ float sx[16][68];     // [kk][row], padded
    __shared__ float sw[16 * 80];    // [kk][col]

    const int tid = threadIdx.x;
    const int m0  = blockIdx.x * 64;
    const int ty  = tid >> 3;
    const int tx  = tid & 7;

    u64 acc[2][5];
#pragma unroll
    for (int r = 0; r < 2; r++)
#pragma unroll
        for (int c = 0; c < 5; c++) acc[r][c] = 0ULL;

    for (int k0 = 0; k0 < KX; k0 += 16) {
        // stage x tile 64x16 via float4 (768 and k0 are multiples of 16 -> aligned)
        {
            const int r = tid >> 2, q4 = tid & 3;
            const float4 xv = *(const float4*)&x[(size_t)(m0 + r) * KX + k0 + q4 * 4];
            sx[q4 * 4 + 0][r] = xv.x;
            sx[q4 * 4 + 1][r] = xv.y;
            sx[q4 * 4 + 2][r] = xv.z;
            sx[q4 * 4 + 3][r] = xv.w;
        }
        // stage Wq tile 16x80
#pragma unroll
        for (int s = 0; s < 5; s++) {
            const int i = tid + s * 256;
            const int kk = i / 80, j = i - kk * 80;
            sw[i] = Wq[(size_t)(k0 + kk) * 80 + j];
        }
        __syncthreads();

#pragma unroll
        for (int kk = 0; kk < 16; kk++) {
            const float xa = sx[kk][ty * 2 + 0];
            const float xb = sx[kk][ty * 2 + 1];
            const u64 xa2 = pack2(xa, xa);
            const u64 xb2 = pack2(xb, xb);
            const u64* wp = (const u64*)&sw[kk * 80 + tx * 10];
#pragma unroll
            for (int c = 0; c < 5; c++) {
                const u64 w2 = wp[c];
                acc[0][c] = ffma2(xa2, w2, acc[0][c]);
                acc[1][c] = ffma2(xb2, w2, acc[1][c]);
            }
        }
        __syncthreads();
    }

    float* o0 = &out[(size_t)(m0 + ty * 2) * DMODEL + tx * 10];
#pragma unroll
    for (int c = 0; c < 5; c++) {
        *(u64*)&o0[2 * c]          = acc[0][c];
        *(u64*)&o0[DMODEL + 2 * c] = acc[1][c];
    }
}

// ---------------- Kernel B: fused K,V projection (y @ [Wk|Wv]) ----------------
// GEMM M=32768, N=160 (80 K cols + 80 V cols), K=283.
// ty = tid>>3 (2 rows), tx = tid&7 (20 cols each, as 10 float2).
__global__ void __launch_bounds__(256) kvproj_kernel(
    const float* __restrict__ y, const float* __restrict__ Wk, const float* __restrict__ Wv)
{
    __shared__ float sx[16][68];
    __shared__ float sw[16 * 160];

    const int tid = threadIdx.x;
    const int m0  = blockIdx.x * 64;
    const int ty  = tid >> 3;
    const int tx  = tid & 7;

    u64 acc[2][10];
#pragma unroll
    for (int r = 0; r < 2; r++)
#pragma unroll
        for (int c = 0; c < 10; c++) acc[r][c] = 0ULL;

    for (int k0 = 0; k0 < KY; k0 += 16) {
        // stage y tile 64x16 (scalar, guarded; row stride 283 is not 16B aligned)
#pragma unroll
        for (int s = 0; s < 4; s++) {
            const int i = tid + s * 256;
            const int r = i >> 4, kk = i & 15;
            const int k = k0 + kk;
            sx[kk][r] = (k < KY) ? y[(size_t)(m0 + r) * KY + k] : 0.0f;
        }
        // stage [Wk|Wv] tile 16x160
#pragma unroll
        for (int s = 0; s < 10; s++) {
            const int i = tid + s * 256;
            const int kk = i / 160, j = i - kk * 160;
            const int k = k0 + kk;
            float w = 0.0f;
            if (k < KY) w = (j < 80) ? Wk[(size_t)k * 80 + j] : Wv[(size_t)k * 80 + (j - 80)];
            sw[i] = w;
        }
        __syncthreads();

#pragma unroll
        for (int kk = 0; kk < 16; kk++) {
            const float xa = sx[kk][ty * 2 + 0];
            const float xb = sx[kk][ty * 2 + 1];
            const u64 xa2 = pack2(xa, xa);
            const u64 xb2 = pack2(xb, xb);
            const u64* wp = (const u64*)&sw[kk * 160 + tx * 20];
#pragma unroll
            for (int c = 0; c < 10; c++) {
                const u64 w2 = wp[c];
                acc[0][c] = ffma2(xa2, w2, acc[0][c]);
                acc[1][c] = ffma2(xb2, w2, acc[1][c]);
            }
        }
        __syncthreads();
    }

    // cols tx*20 .. tx*20+19 : tx<=3 -> K, tx>=4 -> V (clean split at 80)
    const int colbase = tx * 20;
    float* dst = (colbase < 80) ? g_k : g_v;
    const int cb = (colbase < 80) ? colbase : (colbase - 80);
#pragma unroll
    for (int r = 0; r < 2; r++) {
        float* o = &dst[(size_t)(m0 + ty * 2 + r) * DMODEL + cb];
#pragma unroll
        for (int c = 0; c < 10; c++) *(u64*)&o[2 * c] = acc[r][c];
    }
}

// ---------------- Kernel C: attention (in-place on d_out: out = q + softmax(qk')v) ----------------
// One block per (b,h). K,V staged in smem, scale folded into K.
// 8 warps; each warp processes 4 q-rows per pass, single fused pass over 512 keys
// (no max-subtraction needed: |score| <~ 2), online sum(e) and sum(e*v).
#define KPAD 14   // row pad (floats): lane*7 mod 16 is a permutation -> conflict-free LDS.64
#define ATTN_SMEM (2 * NY * KPAD * 4)

__global__ void __launch_bounds__(256) attn_kernel(float* qo)
{
    extern __shared__ float smem[];
    float* sk = smem;               // NY x KPAD (pre-scaled)
    float* sv = smem + NY * KPAD;

    const int b = blockIdx.x >> 3;
    const int h = blockIdx.x & 7;
    const float scale = 0.31622776601683794f;  // 1/sqrt(10)

    for (int i = threadIdx.x; i < NY * DHEAD; i += 256) {
        const int ky = i / DHEAD, d = i - ky * DHEAD;
        const size_t g = (size_t)(b * NY + ky) * DMODEL + h * DHEAD + d;
        sk[ky * KPAD + d] = g_k[g] * scale;
        sv[ky * KPAD + d] = g_v[g];
    }
    __syncthreads();

    const int warp = threadIdx.x >> 5;
    const int lane = threadIdx.x & 31;

    for (int qg = warp; qg < NX / 4; qg += 8) {
        const int q0 = qg * 4;
        u64 qv[4][5], acc[4][5];
        float ssum[4];
#pragma unroll
        for (int r = 0; r < 4; r++) {
            const float* qp = &qo[(size_t)(b * NX + q0 + r) * DMODEL + h * DHEAD];
            ssum[r] = 0.0f;
#pragma unroll
            for (int c = 0; c < 5; c++) {
                qv[r][c]  = *(const u64*)&qp[2 * c];
                acc[r][c] = 0ULL;
            }
        }

#pragma unroll 4
        for (int t = 0; t < 16; t++) {
            const int ky = t * 32 + lane;
            const u64* kp = (const u64*)&sk[ky * KPAD];
            const u64* vp = (const u64*)&sv[ky * KPAD];
            u64 kd[5], vd[5];
#pragma unroll
            for (int c = 0; c < 5; c++) { kd[c] = kp[c]; vd[c] = vp[c]; }
#pragma unroll
            for (int r = 0; r < 4; r++) {
                u64 d2 = 0ULL;
#pragma unroll
                for (int c = 0; c < 5; c++) d2 = ffma2(qv[r][c], kd[c], d2);
                float lo, hi; unpack2(d2, lo, hi);
                const float e = __expf(lo + hi);
                ssum[r] += e;
                const u64 e2 = pack2(e, e);
#pragma unroll
                for (int c = 0; c < 5; c++) acc[r][c] = ffma2(e2, vd[c], acc[r][c]);
            }
        }

#pragma unroll
        for (int r = 0; r < 4; r++) {
#pragma unroll
            for (int o = 16; o > 0; o >>= 1)
                ssum[r] += __shfl_xor_sync(0xffffffffu, ssum[r], o);
#pragma unroll
            for (int c = 0; c < 5; c++)
#pragma unroll
                for (int o = 16; o > 0; o >>= 1)
                    acc[r][c] += __shfl_xor_sync(0xffffffffu, acc[r][c], o) & 0ULL
                               ;  // placeholder removed below
        }
        // NOTE: u64 holds two packed floats; reduce the halves as floats.
        // (The line above is a no-op on purpose; real reduction here:)
#pragma unroll
        for (int r = 0; r < 4; r++) {
            const float inv = 1.0f / ssum[r];
#pragma unroll
            for (int c = 0; c < 5; c++) {
                float lo, hi; unpack2(acc[r][c], lo, hi);
#pragma unroll
                for (int o = 16; o > 0; o >>= 1) {
                    lo += __shfl_xor_sync(0xffffffffu, lo, o);
                    hi += __shfl_xor_sync(0xffffffffu, hi, o);
                }
                if (lane == 0) {
                    float qlo, qhi; unpack2(qv[r][c], qlo, qhi);
                    float* op = &qo[(size_t)(b * NX + q0 + r) * DMODEL + h * DHEAD];
                    *(u64*)&op[2 * c] = pack2(qlo + lo * inv, qhi + hi * inv);
                }
            }
        }
    }
}

extern "C" void kernel_launch(void* const* d_in, const int* in_sizes, int n_in,
                              void* d_out, int out_size)
{
    const float* x  = (const float*)d_in[0];
    const float* y  = (const float*)d_in[1];
    const float* Wq = (const float*)d_in[2];
    const float* Wk = (const float*)d_in[3];
    const float* Wv = (const float*)d_in[4];
    float* out = (float*)d_out;

    cudaFuncSetAttribute(attn_kernel, cudaFuncAttributeMaxDynamicSharedMemorySize, ATTN_SMEM);

    qproj_kernel<<<(BATCH * NX) / 64, 256>>>(x, Wq, out);       // writes q into d_out
    kvproj_kernel<<<(BATCH * NY) / 64, 256>>>(y, Wk, Wv);       // writes g_k, g_v
    attn_kernel<<<BATCH * NHEAD, 256, ATTN_SMEM>>>(out);        // out = q + att, in place
}

// round 2
// speedup vs baseline: 1.1023x; 1.1023x over previous
#include <cuda_runtime.h>

#define BATCH 64
#define NX    512
#define NY    512
#define NHEAD 8
#define DHEAD 10
#define DMODEL 80     // NHEAD*DHEAD
#define KX    768
#define KY    283
#define KY_PAD 288    // ceil(283/16)*16

typedef unsigned long long u64;

// scratch for K/V projections — device globals per harness rules
__device__ float g_k[BATCH * NY * DMODEL];
__device__ float g_v[BATCH * NY * DMODEL];

// ---------------- packed f32x2 helpers ----------------
__device__ __forceinline__ u64 pack2(float lo, float hi) {
    u64 r; asm("mov.b64 %0, {%1, %2};" : "=l"(r) : "f"(lo), "f"(hi)); return r;
}
__device__ __forceinline__ void unpack2(u64 v, float& lo, float& hi) {
    asm("mov.b64 {%0, %1}, %2;" : "=f"(lo), "=f"(hi) : "l"(v));
}
__device__ __forceinline__ u64 ffma2(u64 a, u64 b, u64 c) {
    u64 d; asm("fma.rn.f32x2 %0, %1, %2, %3;" : "=l"(d) : "l"(a), "l"(b), "l"(c)); return d;
}
__device__ __forceinline__ u64 add2(u64 a, u64 b) {
    u64 d; asm("add.rn.f32x2 %0, %1, %2;" : "=l"(d) : "l"(a), "l"(b)); return d;
}

// ---------------- Fused projection kernel ----------------
// blocks [0,256):   Q proj  x @ Wq -> out      (tile 128 rows x 80 cols)
// blocks [256,512): KV proj y @ [Wk|Wv] -> g_k,g_v (tile 128 rows x 160 cols)
// 256 threads; thread tile 4 rows x 10 cols (Q) or 4 rows x 20 cols (KV).
__global__ void __launch_bounds__(256) proj_kernel(
    const float* __restrict__ x, const float* __restrict__ y,
    const float* __restrict__ Wq, const float* __restrict__ Wk,
    const float* __restrict__ Wv, float* __restrict__ out)
{
    __shared__ float sx[16][132];    // [kk][row], 128 rows + pad
    __shared__ float sw[16 * 160];   // [kk][col]

    const int tid = threadIdx.x;
    const int ty  = tid >> 3;        // 0..31 -> rows ty*4 .. ty*4+3
    const int tx  = tid & 7;

    if (blockIdx.x < 256) {
        // ---------------- Q projection ----------------
        const int m0 = blockIdx.x * 128;
        u64 acc[4][5];
#pragma unroll
        for (int r = 0; r < 4; r++)
#pragma unroll
            for (int c = 0; c < 5; c++) acc[r][c] = 0ULL;

        for (int k0 = 0; k0 < KX; k0 += 16) {
            // stage x tile 128x16 via float4 (aligned: 768 & k0 multiples of 16)
#pragma unroll
            for (int s = 0; s < 2; s++) {
                const int i = tid + s * 256;
                const int r = i >> 2, q4 = i & 3;
                const float4 xv = *(const float4*)&x[(size_t)(m0 + r) * KX + k0 + q4 * 4];
                sx[q4 * 4 + 0][r] = xv.x;
                sx[q4 * 4 + 1][r] = xv.y;
                sx[q4 * 4 + 2][r] = xv.z;
                sx[q4 * 4 + 3][r] = xv.w;
            }
            // stage Wq tile 16x80 (stride 80 in sw)
#pragma unroll
            for (int s = 0; s < 5; s++) {
                const int i = tid + s * 256;
                const int kk = i / 80, j = i - kk * 80;
                sw[kk * 80 + j] = Wq[(size_t)(k0 + kk) * 80 + j];
            }
            __syncthreads();

#pragma unroll
            for (int kk = 0; kk < 16; kk++) {
                float xr[4];
#pragma unroll
                for (int j = 0; j < 4; j++) xr[j] = sx[kk][ty * 4 + j];
                const u64* wp = (const u64*)&sw[kk * 80 + tx * 10];
                u64 wd[5];
#pragma unroll
                for (int c = 0; c < 5; c++) wd[c] = wp[c];
#pragma unroll
                for (int j = 0; j < 4; j++) {
                    const u64 x2 = pack2(xr[j], xr[j]);
#pragma unroll
                    for (int c = 0; c < 5; c++)
                        acc[j][c] = ffma2(x2, wd[c], acc[j][c]);
                }
            }
            __syncthreads();
        }

#pragma unroll
        for (int j = 0; j < 4; j++) {
            float* o = &out[(size_t)(m0 + ty * 4 + j) * DMODEL + tx * 10];
#pragma unroll
            for (int c = 0; c < 5; c++) *(u64*)&o[2 * c] = acc[j][c];
        }
    } else {
        // ---------------- KV projection ----------------
        const int m0 = (blockIdx.x - 256) * 128;
        u64 acc[4][10];
#pragma unroll
        for (int r = 0; r < 4; r++)
#pragma unroll
            for (int c = 0; c < 10; c++) acc[r][c] = 0ULL;

        for (int k0 = 0; k0 < KY_PAD; k0 += 16) {
            // stage y tile 128x16 (scalar, guarded; row stride 283 unaligned)
#pragma unroll
            for (int s = 0; s < 8; s++) {
                const int i = tid + s * 256;
                const int r = i >> 4, kk = i & 15;
                const int k = k0 + kk;
                sx[kk][r] = (k < KY) ? y[(size_t)(m0 + r) * KY + k] : 0.0f;
            }
            // stage [Wk|Wv] tile 16x160
#pragma unroll
            for (int s = 0; s < 10; s++) {
                const int i = tid + s * 256;
                const int kk = i / 160, j = i - kk * 160;
                const int k = k0 + kk;
                float w = 0.0f;
                if (k < KY) w = (j < 80) ? Wk[(size_t)k * 80 + j]
                                         : Wv[(size_t)k * 80 + (j - 80)];
                sw[i] = w;
            }
            __syncthreads();

#pragma unroll
            for (int kk = 0; kk < 16; kk++) {
                float xr[4];
#pragma unroll
                for (int j = 0; j < 4; j++) xr[j] = sx[kk][ty * 4 + j];
                const u64* wp = (const u64*)&sw[kk * 160 + tx * 20];
                u64 wd[10];
#pragma unroll
                for (int c = 0; c < 10; c++) wd[c] = wp[c];
#pragma unroll
                for (int j = 0; j < 4; j++) {
                    const u64 x2 = pack2(xr[j], xr[j]);
#pragma unroll
                    for (int c = 0; c < 10; c++)
                        acc[j][c] = ffma2(x2, wd[c], acc[j][c]);
                }
            }
            __syncthreads();
        }

        // cols tx*20 .. tx*20+19 : tx<=3 -> K, tx>=4 -> V (clean split at 80)
        const int colbase = tx * 20;
        float* dst = (colbase < 80) ? g_k : g_v;
        const int cb = (colbase < 80) ? colbase : (colbase - 80);
#pragma unroll
        for (int j = 0; j < 4; j++) {
            float* o = &dst[(size_t)(m0 + ty * 4 + j) * DMODEL + cb];
#pragma unroll
            for (int c = 0; c < 10; c++) *(u64*)&o[2 * c] = acc[j][c];
        }
    }
}

// ---------------- Attention (in-place on d_out: out = q + softmax(q k^T / sqrt(dk)) v) ----
// One block per (b,h). K (pre-scaled) and V staged in smem.
// 8 warps; each warp owns 4 q-rows per pass; single fused pass over 512 keys
// (|score| <~ 2 so no max-subtraction), online sum(e) and sum(e*v).
#define KPAD 14   // row pad (floats): lane*7 mod 16 is a permutation -> conflict-free LDS.64
#define ATTN_SMEM (2 * NY * KPAD * 4)

__global__ void __launch_bounds__(256) attn_kernel(float* __restrict__ qo)
{
    extern __shared__ float smem[];
    float* sk = smem;               // NY x KPAD (pre-scaled)
    float* sv = smem + NY * KPAD;

    const int b = blockIdx.x >> 3;
    const int h = blockIdx.x & 7;
    const float scale = 0.31622776601683794f;  // 1/sqrt(10)

    for (int i = threadIdx.x; i < NY * DHEAD; i += 256) {
        const int ky = i / DHEAD, d = i - ky * DHEAD;
        const size_t g = (size_t)(b * NY + ky) * DMODEL + h * DHEAD + d;
        sk[ky * KPAD + d] = g_k[g] * scale;
        sv[ky * KPAD + d] = g_v[g];
    }
    __syncthreads();

    const int warp = threadIdx.x >> 5;
    const int lane = threadIdx.x & 31;

    for (int qg = warp; qg < NX / 4; qg += 8) {
        const int q0 = qg * 4;
        u64 qv[4][5], acc[4][5];
        float ssum[4];
#pragma unroll
        for (int r = 0; r < 4; r++) {
            const float* qp = &qo[(size_t)(b * NX + q0 + r) * DMODEL + h * DHEAD];
            ssum[r] = 0.0f;
#pragma unroll
            for (int c = 0; c < 5; c++) {
                qv[r][c]  = *(const u64*)&qp[2 * c];
                acc[r][c] = 0ULL;
            }
        }

#pragma unroll 4
        for (int t = 0; t < 16; t++) {
            const int ky = t * 32 + lane;
            const u64* kp = (const u64*)&sk[ky * KPAD];
            const u64* vp = (const u64*)&sv[ky * KPAD];
            u64 kd[5], vd[5];
#pragma unroll
            for (int c = 0; c < 5; c++) { kd[c] = kp[c]; vd[c] = vp[c]; }
#pragma unroll
            for (int r = 0; r < 4; r++) {
                u64 d2 = 0ULL;
#pragma unroll
                for (int c = 0; c < 5; c++) d2 = ffma2(qv[r][c], kd[c], d2);
                float lo, hi; unpack2(d2, lo, hi);
                const float e = __expf(lo + hi);
                ssum[r] += e;
                const u64 e2 = pack2(e, e);
#pragma unroll
                for (int c = 0; c < 5; c++) acc[r][c] = ffma2(e2, vd[c], acc[r][c]);
            }
        }

        // cross-lane reduction: packed f32x2 adds over u64 shuffles
#pragma unroll
        for (int r = 0; r < 4; r++) {
#pragma unroll
            for (int o = 16; o > 0; o >>= 1)
                ssum[r] += __shfl_xor_sync(0xffffffffu, ssum[r], o);
            const float inv = 1.0f / ssum[r];
#pragma unroll
            for (int c = 0; c < 5; c++) {
                u64 a = acc[r][c];
#pragma unroll
                for (int o = 16; o > 0; o >>= 1)
                    a = add2(a, __shfl_xor_sync(0xffffffffu, a, o));
                if (lane == 0) {
                    float lo, hi;  unpack2(a, lo, hi);
                    float qlo, qhi; unpack2(qv[r][c], qlo, qhi);
                    float* op = &qo[(size_t)(b * NX + q0 + r) * DMODEL + h * DHEAD];
                    *(u64*)&op[2 * c] = pack2(qlo + lo * inv, qhi + hi * inv);
                }
            }
        }
    }
}

extern "C" void kernel_launch(void* const* d_in, const int* in_sizes, int n_in,
                              void* d_out, int out_size)
{
    const float* x  = (const float*)d_in[0];
    const float* y  = (const float*)d_in[1];
    const float* Wq = (const float*)d_in[2];
    const float* Wk = (const float*)d_in[3];
    const float* Wv = (const float*)d_in[4];
    float* out = (float*)d_out;

    cudaFuncSetAttribute(attn_kernel, cudaFuncAttributeMaxDynamicSharedMemorySize, ATTN_SMEM);

    proj_kernel<<<512, 256>>>(x, y, Wq, Wk, Wv, out);   // q -> d_out, k/v -> g_k/g_v
    attn_kernel<<<BATCH * NHEAD, 256, ATTN_SMEM>>>(out); // out = q + att, in place
}

// round 4
// speedup vs baseline: 1.5754x; 1.4292x over previous
#include <cuda_runtime.h>

#define BATCH 64
#define NX    512
#define NY    512
#define NHEAD 8
#define DHEAD 10
#define DMODEL 80     // NHEAD*DHEAD
#define KX    768
#define KY    283
#define KY_PAD 288    // ceil(283/16)*16

typedef unsigned long long u64;

// scratch for K/V projections — device globals per harness rules
__device__ float g_k[BATCH * NY * DMODEL];
__device__ float g_v[BATCH * NY * DMODEL];

// ---------------- packed f32x2 helpers ----------------
__device__ __forceinline__ u64 pack2(float lo, float hi) {
    u64 r; asm("mov.b64 %0, {%1, %2};" : "=l"(r) : "f"(lo), "f"(hi)); return r;
}
__device__ __forceinline__ void unpack2(u64 v, float& lo, float& hi) {
    asm("mov.b64 {%0, %1}, %2;" : "=f"(lo), "=f"(hi) : "l"(v));
}
__device__ __forceinline__ u64 ffma2(u64 a, u64 b, u64 c) {
    u64 d; asm("fma.rn.f32x2 %0, %1, %2, %3;" : "=l"(d) : "l"(a), "l"(b), "l"(c)); return d;
}
__device__ __forceinline__ u64 add2(u64 a, u64 b) {
    u64 d; asm("add.rn.f32x2 %0, %1, %2;" : "=l"(d) : "l"(a), "l"(b)); return d;
}

// ---------------- Generic projection kernel ----------------
// 768 blocks: [0,256) Q = x@Wq -> out ; [256,512) K = y@Wk -> g_k ; [512,768) V = y@Wv -> g_v
// Block tile: 128 rows x 80 cols, 256 threads, thread tile 4 rows x 10 cols.
// Inner loop per kk: 1 LDS.128 (x, 4 rows) + 5 LDS.64 (W) -> 20 FFMA2.
__global__ void __launch_bounds__(256) proj_kernel(
    const float* __restrict__ x, const float* __restrict__ y,
    const float* __restrict__ Wq, const float* __restrict__ Wk,
    const float* __restrict__ Wv, float* __restrict__ out)
{
    __shared__ __align__(16) float sx[16][132];  // [kk][row], 128 rows + pad (row = 528B, mult of 16)
    __shared__ __align__(16) float sw[16 * 80];  // [kk][col]

    const int tid   = threadIdx.x;
    const int ty    = tid >> 3;      // 0..31 -> rows ty*4 .. ty*4+3
    const int tx    = tid & 7;       // cols tx*10 .. tx*10+9
    const int which = blockIdx.x >> 8;          // 0=Q, 1=K, 2=V
    const int m0    = (blockIdx.x & 255) * 128;

    const float* in = (which == 0) ? x : y;
    const float* W  = (which == 0) ? Wq : ((which == 1) ? Wk : Wv);
    float* dst      = (which == 0) ? out : ((which == 1) ? g_k : g_v);
    const int Kdim  = (which == 0) ? KX : KY;
    const int Kpad  = (which == 0) ? KX : KY_PAD;

    u64 acc[4][5];
#pragma unroll
    for (int r = 0; r < 4; r++)
#pragma unroll
        for (int c = 0; c < 5; c++) acc[r][c] = 0ULL;

    for (int k0 = 0; k0 < Kpad; k0 += 16) {
        // ---- stage input tile 128x16 ----
        if (which == 0) {
            // x: rows are 16-float aligned -> float4 path
#pragma unroll
            for (int s = 0; s < 2; s++) {
                const int i = tid + s * 256;
                const int r = i >> 2, q4 = i & 3;
                const float4 xv = *(const float4*)&x[(size_t)(m0 + r) * KX + k0 + q4 * 4];
                sx[q4 * 4 + 0][r] = xv.x;
                sx[q4 * 4 + 1][r] = xv.y;
                sx[q4 * 4 + 2][r] = xv.z;
                sx[q4 * 4 + 3][r] = xv.w;
            }
        } else {
            // y: stride 283, scalar guarded
#pragma unroll
            for (int s = 0; s < 8; s++) {
                const int i = tid + s * 256;
                const int r = i >> 4, kk = i & 15;
                const int k = k0 + kk;
                sx[kk][r] = (k < Kdim) ? in[(size_t)(m0 + r) * Kdim + k] : 0.0f;
            }
        }
        // ---- stage W tile 16x80 ----
#pragma unroll
        for (int s = 0; s < 5; s++) {
            const int i = tid + s * 256;
            const int kk = i / 80, j = i - kk * 80;
            const int k = k0 + kk;
            sw[i] = (k < Kdim) ? W[(size_t)k * 80 + j] : 0.0f;
        }
        __syncthreads();

#pragma unroll
        for (int kk = 0; kk < 16; kk++) {
            const float4 xv = *(const float4*)&sx[kk][ty * 4];   // 4 rows, one LDS.128
            const u64* wp = (const u64*)&sw[kk * 80 + tx * 10];  // 40B offset: 8B-aligned
            u64 wd[5];
#pragma unroll
            for (int c = 0; c < 5; c++) wd[c] = wp[c];
            const u64 x0 = pack2(xv.x, xv.x);
            const u64 x1 = pack2(xv.y, xv.y);
            const u64 x2 = pack2(xv.z, xv.z);
            const u64 x3 = pack2(xv.w, xv.w);
#pragma unroll
            for (int c = 0; c < 5; c++) {
                acc[0][c] = ffma2(x0, wd[c], acc[0][c]);
                acc[1][c] = ffma2(x1, wd[c], acc[1][c]);
                acc[2][c] = ffma2(x2, wd[c], acc[2][c]);
                acc[3][c] = ffma2(x3, wd[c], acc[3][c]);
            }
        }
        __syncthreads();
    }

#pragma unroll
    for (int j = 0; j < 4; j++) {
        float* o = &dst[(size_t)(m0 + ty * 4 + j) * DMODEL + tx * 10];
#pragma unroll
        for (int c = 0; c < 5; c++) *(u64*)&o[2 * c] = acc[j][c];
    }
}

// ---------------- Attention (in-place on d_out: out = q + softmax(q k^T / sqrt(dk)) v) ----
// One block per (b,h). K (pre-scaled) and V staged in smem.
// 8 warps; each warp owns 4 q-rows per pass; single fused pass over 512 keys
// (|score| <~ 2 so no max-subtraction), online sum(e) and sum(e*v).
// KPAD=14: rows are 56B (8B-aligned for LDS.64); lane stride 56B mod 128B covers
// all 16 8-byte slots per 16-lane phase -> conflict-free 64-bit loads.
#define KPAD 14
#define ATTN_SMEM (2 * NY * KPAD * 4)

__global__ void __launch_bounds__(256) attn_kernel(float* __restrict__ qo)
{
    extern __shared__ float smem[];
    float* sk = smem;               // NY x KPAD (pre-scaled)
    float* sv = smem + NY * KPAD;

    const int b = blockIdx.x >> 3;
    const int h = blockIdx.x & 7;
    const float scale = 0.31622776601683794f;  // 1/sqrt(10)

    for (int i = threadIdx.x; i < NY * DHEAD; i += 256) {
        const int ky = i / DHEAD, d = i - ky * DHEAD;
        const size_t g = (size_t)(b * NY + ky) * DMODEL + h * DHEAD + d;
        sk[ky * KPAD + d] = g_k[g] * scale;
        sv[ky * KPAD + d] = g_v[g];
    }
    __syncthreads();

    const int warp = threadIdx.x >> 5;
    const int lane = threadIdx.x & 31;

    for (int qg = warp; qg < NX / 4; qg += 8) {
        const int q0 = qg * 4;
        u64 qv[4][5], acc[4][5];
        float ssum[4];
#pragma unroll
        for (int r = 0; r < 4; r++) {
            const float* qp = &qo[(size_t)(b * NX + q0 + r) * DMODEL + h * DHEAD];
            ssum[r] = 0.0f;
#pragma unroll
            for (int c = 0; c < 5; c++) {
                qv[r][c]  = *(const u64*)&qp[2 * c];
                acc[r][c] = 0ULL;
            }
        }

#pragma unroll 4
        for (int t = 0; t < 16; t++) {
            const int ky = t * 32 + lane;
            const u64* kp = (const u64*)&sk[ky * KPAD];
            const u64* vp = (const u64*)&sv[ky * KPAD];
            u64 kd[5], vd[5];
#pragma unroll
            for (int c = 0; c < 5; c++) { kd[c] = kp[c]; vd[c] = vp[c]; }
#pragma unroll
            for (int r = 0; r < 4; r++) {
                u64 d2 = 0ULL;
#pragma unroll
                for (int c = 0; c < 5; c++) d2 = ffma2(qv[r][c], kd[c], d2);
                float lo, hi; unpack2(d2, lo, hi);
                const float e = __expf(lo + hi);
                ssum[r] += e;
                const u64 e2 = pack2(e, e);
#pragma unroll
                for (int c = 0; c < 5; c++) acc[r][c] = ffma2(e2, vd[c], acc[r][c]);
            }
        }

        // cross-lane reduction: packed f32x2 adds over u64 shuffles
#pragma unroll
        for (int r = 0; r < 4; r++) {
#pragma unroll
            for (int o = 16; o > 0; o >>= 1)
                ssum[r] += __shfl_xor_sync(0xffffffffu, ssum[r], o);
            const float inv = 1.0f / ssum[r];
#pragma unroll
            for (int c = 0; c < 5; c++) {
                u64 a = acc[r][c];
#pragma unroll
                for (int o = 16; o > 0; o >>= 1)
                    a = add2(a, __shfl_xor_sync(0xffffffffu, a, o));
                if (lane == 0) {
                    float lo, hi;  unpack2(a, lo, hi);
                    float qlo, qhi; unpack2(qv[r][c], qlo, qhi);
                    float* op = &qo[(size_t)(b * NX + q0 + r) * DMODEL + h * DHEAD];
                    *(u64*)&op[2 * c] = pack2(qlo + lo * inv, qhi + hi * inv);
                }
            }
        }
    }
}

extern "C" void kernel_launch(void* const* d_in, const int* in_sizes, int n_in,
                              void* d_out, int out_size)
{
    const float* x  = (const float*)d_in[0];
    const float* y  = (const float*)d_in[1];
    const float* Wq = (const float*)d_in[2];
    const float* Wk = (const float*)d_in[3];
    const float* Wv = (const float*)d_in[4];
    float* out = (float*)d_out;

    cudaFuncSetAttribute(attn_kernel, cudaFuncAttributeMaxDynamicSharedMemorySize, ATTN_SMEM);

    proj_kernel<<<768, 256>>>(x, y, Wq, Wk, Wv, out);    // q -> d_out, k/v -> g_k/g_v
    attn_kernel<<<BATCH * NHEAD, 256, ATTN_SMEM>>>(out); // out = q + att, in place
}

// round 5
// speedup vs baseline: 1.7585x; 1.1162x over previous
#include <cuda_runtime.h>

#define BATCH 64
#define NX    512
#define NY    512
#define NHEAD 8
#define DHEAD 10
#define DMODEL 80     // NHEAD*DHEAD
#define KX    768
#define KY    283
#define KY_PAD 288    // ceil(283/16)*16

typedef unsigned long long u64;

// scratch for K/V projections — device globals per harness rules
__device__ float g_k[BATCH * NY * DMODEL];
__device__ float g_v[BATCH * NY * DMODEL];

// ---------------- packed f32x2 helpers ----------------
__device__ __forceinline__ u64 pack2(float lo, float hi) {
    u64 r; asm("mov.b64 %0, {%1, %2};" : "=l"(r) : "f"(lo), "f"(hi)); return r;
}
__device__ __forceinline__ void unpack2(u64 v, float& lo, float& hi) {
    asm("mov.b64 {%0, %1}, %2;" : "=f"(lo), "=f"(hi) : "l"(v));
}
__device__ __forceinline__ u64 ffma2(u64 a, u64 b, u64 c) {
    u64 d; asm("fma.rn.f32x2 %0, %1, %2, %3;" : "=l"(d) : "l"(a), "l"(b), "l"(c)); return d;
}
__device__ __forceinline__ u64 add2(u64 a, u64 b) {
    u64 d; asm("add.rn.f32x2 %0, %1, %2;" : "=l"(d) : "l"(a), "l"(b)); return d;
}

// ---------------- Generic projection kernel (double-buffered) ----------------
// 768 blocks: [0,256) Q = x@Wq -> out ; [256,512) K = y@Wk -> g_k ; [512,768) V = y@Wv -> g_v
// Block tile: 128 rows x 80 cols, 256 threads, thread tile 4 rows x 10 cols.
// Smem ping-pong: prefetch tile t+1 into registers during compute of tile t;
// one __syncthreads per tile.
__global__ void __launch_bounds__(256) proj_kernel(
    const float* __restrict__ x, const float* __restrict__ y,
    const float* __restrict__ Wq, const float* __restrict__ Wk,
    const float* __restrict__ Wv, float* __restrict__ out)
{
    __shared__ __align__(16) float sx[2][16][132];  // [buf][kk][row] (row = 528B, mult of 16)
    __shared__ __align__(16) float sw[2][16 * 80];  // [buf][kk*80 + col]

    const int tid   = threadIdx.x;
    const int ty    = tid >> 3;      // 0..31 -> rows ty*4 .. ty*4+3
    const int tx    = tid & 7;       // cols tx*10 .. tx*10+9
    const int which = blockIdx.x >> 8;          // 0=Q, 1=K, 2=V
    const int m0    = (blockIdx.x & 255) * 128;

    const float* in = (which == 0) ? x : y;
    const float* W  = (which == 0) ? Wq : ((which == 1) ? Wk : Wv);
    float* dst      = (which == 0) ? out : ((which == 1) ? g_k : g_v);
    const int Kdim  = (which == 0) ? KX : KY;
    const int ntile = ((which == 0) ? KX : KY_PAD) >> 4;

    float4 pfx[2];   // Q path prefetch (x, aligned float4)
    float  pfy[8];   // KV path prefetch (y, scalar guarded)
    float  pfw[5];   // W prefetch

    auto load_tile = [&](int t) {
        const int k0 = t << 4;
        if (which == 0) {
#pragma unroll
            for (int s = 0; s < 2; s++) {
                const int i = tid + s * 256;
                const int r = i >> 2, q4 = i & 3;
                pfx[s] = *(const float4*)&x[(size_t)(m0 + r) * KX + k0 + q4 * 4];
            }
        } else {
#pragma unroll
            for (int s = 0; s < 8; s++) {
                const int i = tid + s * 256;
                const int r = i >> 4, kk = i & 15;
                const int k = k0 + kk;
                pfy[s] = (k < Kdim) ? in[(size_t)(m0 + r) * Kdim + k] : 0.0f;
            }
        }
#pragma unroll
        for (int s = 0; s < 5; s++) {
            const int i = tid + s * 256;
            const int kk = i / 80, j = i - kk * 80;
            const int k = k0 + kk;
            pfw[s] = (k < Kdim) ? W[(size_t)k * 80 + j] : 0.0f;
        }
    };
    auto store_tile = [&](int buf) {
        if (which == 0) {
#pragma unroll
            for (int s = 0; s < 2; s++) {
                const int i = tid + s * 256;
                const int r = i >> 2, q4 = i & 3;
                sx[buf][q4 * 4 + 0][r] = pfx[s].x;
                sx[buf][q4 * 4 + 1][r] = pfx[s].y;
                sx[buf][q4 * 4 + 2][r] = pfx[s].z;
                sx[buf][q4 * 4 + 3][r] = pfx[s].w;
            }
        } else {
#pragma unroll
            for (int s = 0; s < 8; s++) {
                const int i = tid + s * 256;
                const int r = i >> 4, kk = i & 15;
                sx[buf][kk][r] = pfy[s];
            }
        }
#pragma unroll
        for (int s = 0; s < 5; s++) sw[buf][tid + s * 256] = pfw[s];
    };

    u64 acc[4][5];
#pragma unroll
    for (int r = 0; r < 4; r++)
#pragma unroll
        for (int c = 0; c < 5; c++) acc[r][c] = 0ULL;

    load_tile(0);
    store_tile(0);
    __syncthreads();

    for (int t = 0; t < ntile; t++) {
        const int cur = t & 1;
        const bool more = (t + 1 < ntile);
        if (more) load_tile(t + 1);

#pragma unroll
        for (int kk = 0; kk < 16; kk++) {
            const float4 xv = *(const float4*)&sx[cur][kk][ty * 4];   // 4 rows, one LDS.128
            const u64* wp = (const u64*)&sw[cur][kk * 80 + tx * 10];  // 40B offset: 8B-aligned
            u64 wd[5];
#pragma unroll
            for (int c = 0; c < 5; c++) wd[c] = wp[c];
            const u64 x0 = pack2(xv.x, xv.x);
            const u64 x1 = pack2(xv.y, xv.y);
            const u64 x2 = pack2(xv.z, xv.z);
            const u64 x3 = pack2(xv.w, xv.w);
#pragma unroll
            for (int c = 0; c < 5; c++) {
                acc[0][c] = ffma2(x0, wd[c], acc[0][c]);
                acc[1][c] = ffma2(x1, wd[c], acc[1][c]);
                acc[2][c] = ffma2(x2, wd[c], acc[2][c]);
                acc[3][c] = ffma2(x3, wd[c], acc[3][c]);
            }
        }

        if (more) store_tile((t + 1) & 1);
        __syncthreads();
    }

#pragma unroll
    for (int j = 0; j < 4; j++) {
        float* o = &dst[(size_t)(m0 + ty * 4 + j) * DMODEL + tx * 10];
#pragma unroll
        for (int c = 0; c < 5; c++) *(u64*)&o[2 * c] = acc[j][c];
    }
}

// ---------------- Attention (in-place on d_out: out = q + softmax(q k^T / sqrt(dk)) v) ----
// One block per (b,h). K (pre-scaled) and V staged in smem.
// KPAD=20 floats (80B): rows 16B-aligned; LDS.128 chunk index ky*5 mod 8 is a
// permutation -> conflict-free .128; tail LDS.64 has a benign 2-way conflict.
// 8 warps; each warp owns 4 q-rows per pass; single fused pass over 512 keys
// (|score| <~ 2 so no max-subtraction), online sum(e) and sum(e*v).
#define KPAD 20
#define ATTN_SMEM (2 * NY * KPAD * 4)

__global__ void __launch_bounds__(256) attn_kernel(float* __restrict__ qo)
{
    extern __shared__ __align__(16) float smem[];
    float* sk = smem;               // NY x KPAD (pre-scaled)
    float* sv = smem + NY * KPAD;

    const int b = blockIdx.x >> 3;
    const int h = blockIdx.x & 7;
    const float scale = 0.31622776601683794f;  // 1/sqrt(10)

    for (int i = threadIdx.x; i < NY * DHEAD; i += 256) {
        const int ky = i / DHEAD, d = i - ky * DHEAD;
        const size_t g = (size_t)(b * NY + ky) * DMODEL + h * DHEAD + d;
        sk[ky * KPAD + d] = g_k[g] * scale;
        sv[ky * KPAD + d] = g_v[g];
    }
    __syncthreads();

    const int warp = threadIdx.x >> 5;
    const int lane = threadIdx.x & 31;

    for (int qg = warp; qg < NX / 4; qg += 8) {
        const int q0 = qg * 4;
        u64 qv[4][5], acc[4][5];
        float ssum[4];
#pragma unroll
        for (int r = 0; r < 4; r++) {
            const float* qp = &qo[(size_t)(b * NX + q0 + r) * DMODEL + h * DHEAD];
            ssum[r] = 0.0f;
#pragma unroll
            for (int c = 0; c < 5; c++) {
                qv[r][c]  = *(const u64*)&qp[2 * c];
                acc[r][c] = 0ULL;
            }
        }

#pragma unroll 4
        for (int t = 0; t < 16; t++) {
            const int ky = t * 32 + lane;
            const float* krow = &sk[ky * KPAD];
            const float* vrow = &sv[ky * KPAD];
            // K row: 2 x LDS.128 + 1 x LDS.64
            const ulonglong2 k01 = *(const ulonglong2*)(krow);
            const ulonglong2 k23 = *(const ulonglong2*)(krow + 4);
            const u64        k4  = *(const u64*)(krow + 8);
            const ulonglong2 v01 = *(const ulonglong2*)(vrow);
            const ulonglong2 v23 = *(const ulonglong2*)(vrow + 4);
            const u64        v4  = *(const u64*)(vrow + 8);
            const u64 kd[5] = { k01.x, k01.y, k23.x, k23.y, k4 };
            const u64 vd[5] = { v01.x, v01.y, v23.x, v23.y, v4 };
#pragma unroll
            for (int r = 0; r < 4; r++) {
                u64 d2 = 0ULL;
#pragma unroll
                for (int c = 0; c < 5; c++) d2 = ffma2(qv[r][c], kd[c], d2);
                float lo, hi; unpack2(d2, lo, hi);
                const float e = __expf(lo + hi);
                ssum[r] += e;
                const u64 e2 = pack2(e, e);
#pragma unroll
                for (int c = 0; c < 5; c++) acc[r][c] = ffma2(e2, vd[c], acc[r][c]);
            }
        }

        // cross-lane reduction: packed f32x2 adds over u64 shuffles
#pragma unroll
        for (int r = 0; r < 4; r++) {
#pragma unroll
            for (int o = 16; o > 0; o >>= 1)
                ssum[r] += __shfl_xor_sync(0xffffffffu, ssum[r], o);
            const float inv = 1.0f / ssum[r];
#pragma unroll
            for (int c = 0; c < 5; c++) {
                u64 a = acc[r][c];
#pragma unroll
                for (int o = 16; o > 0; o >>= 1)
                    a = add2(a, __shfl_xor_sync(0xffffffffu, a, o));
                if (lane == 0) {
                    float lo, hi;  unpack2(a, lo, hi);
                    float qlo, qhi; unpack2(qv[r][c], qlo, qhi);
                    float* op = &qo[(size_t)(b * NX + q0 + r) * DMODEL + h * DHEAD];
                    *(u64*)&op[2 * c] = pack2(qlo + lo * inv, qhi + hi * inv);
                }
            }
        }
    }
}

extern "C" void kernel_launch(void* const* d_in, const int* in_sizes, int n_in,
                              void* d_out, int out_size)
{
    const float* x  = (const float*)d_in[0];
    const float* y  = (const float*)d_in[1];
    const float* Wq = (const float*)d_in[2];
    const float* Wk = (const float*)d_in[3];
    const float* Wv = (const float*)d_in[4];
    float* out = (float*)d_out;

    cudaFuncSetAttribute(attn_kernel, cudaFuncAttributeMaxDynamicSharedMemorySize, ATTN_SMEM);

    proj_kernel<<<768, 256>>>(x, y, Wq, Wk, Wv, out);    // q -> d_out, k/v -> g_k/g_v
    attn_kernel<<<BATCH * NHEAD, 256, ATTN_SMEM>>>(out); // out = q + att, in place
}

// round 6
// speedup vs baseline: 1.8266x; 1.0388x over previous
#include <cuda_runtime.h>

#define BATCH 64
#define NX    512
#define NY    512
#define NHEAD 8
#define DHEAD 10
#define DMODEL 80     // NHEAD*DHEAD
#define KX    768
#define KY    283
#define KY_PAD 288    // ceil(283/16)*16

typedef unsigned long long u64;

// scratch for K/V projections — device globals per harness rules
__device__ float g_k[BATCH * NY * DMODEL];
__device__ float g_v[BATCH * NY * DMODEL];

// ---------------- packed f32x2 helpers ----------------
__device__ __forceinline__ u64 pack2(float lo, float hi) {
    u64 r; asm("mov.b64 %0, {%1, %2};" : "=l"(r) : "f"(lo), "f"(hi)); return r;
}
__device__ __forceinline__ void unpack2(u64 v, float& lo, float& hi) {
    asm("mov.b64 {%0, %1}, %2;" : "=f"(lo), "=f"(hi) : "l"(v));
}
__device__ __forceinline__ u64 ffma2(u64 a, u64 b, u64 c) {
    u64 d; asm("fma.rn.f32x2 %0, %1, %2, %3;" : "=l"(d) : "l"(a), "l"(b), "l"(c)); return d;
}
__device__ __forceinline__ u64 add2(u64 a, u64 b) {
    u64 d; asm("add.rn.f32x2 %0, %1, %2;" : "=l"(d) : "l"(a), "l"(b)); return d;
}
__device__ __forceinline__ u64 mul2(u64 a, u64 b) {
    u64 d; asm("mul.rn.f32x2 %0, %1, %2;" : "=l"(d) : "l"(a), "l"(b)); return d;
}

// ---------------- Generic projection kernel (double-buffered) ----------------
// 768 blocks: [0,256) Q = x@Wq -> out ; [256,512) K = y@Wk -> g_k ; [512,768) V = y@Wv -> g_v
// Block tile: 128 rows x 80 cols, 256 threads, thread tile 4 rows x 10 cols.
__global__ void __launch_bounds__(256) proj_kernel(
    const float* __restrict__ x, const float* __restrict__ y,
    const float* __restrict__ Wq, const float* __restrict__ Wk,
    const float* __restrict__ Wv, float* __restrict__ out)
{
    __shared__ __align__(16) float sx[2][16][132];  // [buf][kk][row]
    __shared__ __align__(16) float sw[2][16 * 80];  // [buf][kk*80 + col]

    const int tid   = threadIdx.x;
    const int ty    = tid >> 3;
    const int tx    = tid & 7;
    const int which = blockIdx.x >> 8;          // 0=Q, 1=K, 2=V
    const int m0    = (blockIdx.x & 255) * 128;

    const float* in = (which == 0) ? x : y;
    const float* W  = (which == 0) ? Wq : ((which == 1) ? Wk : Wv);
    float* dst      = (which == 0) ? out : ((which == 1) ? g_k : g_v);
    const int Kdim  = (which == 0) ? KX : KY;
    const int ntile = ((which == 0) ? KX : KY_PAD) >> 4;

    float4 pfx[2];
    float  pfy[8];
    float  pfw[5];

    auto load_tile = [&](int t) {
        const int k0 = t << 4;
        if (which == 0) {
#pragma unroll
            for (int s = 0; s < 2; s++) {
                const int i = tid + s * 256;
                const int r = i >> 2, q4 = i & 3;
                pfx[s] = *(const float4*)&x[(size_t)(m0 + r) * KX + k0 + q4 * 4];
            }
        } else {
#pragma unroll
            for (int s = 0; s < 8; s++) {
                const int i = tid + s * 256;
                const int r = i >> 4, kk = i & 15;
                const int k = k0 + kk;
                pfy[s] = (k < Kdim) ? in[(size_t)(m0 + r) * Kdim + k] : 0.0f;
            }
        }
#pragma unroll
        for (int s = 0; s < 5; s++) {
            const int i = tid + s * 256;
            const int kk = i / 80, j = i - kk * 80;
            const int k = k0 + kk;
            pfw[s] = (k < Kdim) ? W[(size_t)k * 80 + j] : 0.0f;
        }
    };
    auto store_tile = [&](int buf) {
        if (which == 0) {
#pragma unroll
            for (int s = 0; s < 2; s++) {
                const int i = tid + s * 256;
                const int r = i >> 2, q4 = i & 3;
                sx[buf][q4 * 4 + 0][r] = pfx[s].x;
                sx[buf][q4 * 4 + 1][r] = pfx[s].y;
                sx[buf][q4 * 4 + 2][r] = pfx[s].z;
                sx[buf][q4 * 4 + 3][r] = pfx[s].w;
            }
        } else {
#pragma unroll
            for (int s = 0; s < 8; s++) {
                const int i = tid + s * 256;
                const int r = i >> 4, kk = i & 15;
                sx[buf][kk][r] = pfy[s];
            }
        }
#pragma unroll
        for (int s = 0; s < 5; s++) sw[buf][tid + s * 256] = pfw[s];
    };

    u64 acc[4][5];
#pragma unroll
    for (int r = 0; r < 4; r++)
#pragma unroll
        for (int c = 0; c < 5; c++) acc[r][c] = 0ULL;

    load_tile(0);
    store_tile(0);
    __syncthreads();

    for (int t = 0; t < ntile; t++) {
        const int cur = t & 1;
        const bool more = (t + 1 < ntile);
        if (more) load_tile(t + 1);

#pragma unroll
        for (int kk = 0; kk < 16; kk++) {
            const float4 xv = *(const float4*)&sx[cur][kk][ty * 4];
            const u64* wp = (const u64*)&sw[cur][kk * 80 + tx * 10];
            u64 wd[5];
#pragma unroll
            for (int c = 0; c < 5; c++) wd[c] = wp[c];
            const u64 x0 = pack2(xv.x, xv.x);
            const u64 x1 = pack2(xv.y, xv.y);
            const u64 x2 = pack2(xv.z, xv.z);
            const u64 x3 = pack2(xv.w, xv.w);
#pragma unroll
            for (int c = 0; c < 5; c++) {
                acc[0][c] = ffma2(x0, wd[c], acc[0][c]);
                acc[1][c] = ffma2(x1, wd[c], acc[1][c]);
                acc[2][c] = ffma2(x2, wd[c], acc[2][c]);
                acc[3][c] = ffma2(x3, wd[c], acc[3][c]);
            }
        }

        if (more) store_tile((t + 1) & 1);
        __syncthreads();
    }

#pragma unroll
    for (int j = 0; j < 4; j++) {
        float* o = &dst[(size_t)(m0 + ty * 4 + j) * DMODEL + tx * 10];
#pragma unroll
        for (int c = 0; c < 5; c++) *(u64*)&o[2 * c] = acc[j][c];
    }
}

// ---------------- Attention v2: lane = q-row, broadcast K/V ----------------
// One block per (b,h). K (pre-scaled) and V staged in smem (KPAD=20, 16B rows).
// Each lane owns one q-row (q, acc, softmax sum in registers). The warp walks
// all 512 keys with BROADCAST smem reads (all lanes same address -> N=1):
// one 160B K+V read serves 32 q-rows -> 8x less crossbar traffic than v1,
// and no cross-lane reduction at all.
// 2 passes: 8 warps x 32 lanes = 256 rows per pass, 512 rows total.
// No max-subtraction (|score| <~ 2), single fused pass, out = q + softmax*V.
#define KPAD 20
#define ATTN_SMEM (2 * NY * KPAD * 4)

__global__ void __launch_bounds__(256) attn_kernel(float* __restrict__ qo)
{
    extern __shared__ __align__(16) float smem[];
    float* sk = smem;               // NY x KPAD (pre-scaled)
    float* sv = smem + NY * KPAD;

    const int b = blockIdx.x >> 3;
    const int h = blockIdx.x & 7;
    const float scale = 0.31622776601683794f;  // 1/sqrt(10)

    for (int i = threadIdx.x; i < NY * DHEAD; i += 256) {
        const int ky = i / DHEAD, d = i - ky * DHEAD;
        const size_t g = (size_t)(b * NY + ky) * DMODEL + h * DHEAD + d;
        sk[ky * KPAD + d] = g_k[g] * scale;
        sv[ky * KPAD + d] = g_v[g];
    }
    __syncthreads();

    const int warp = threadIdx.x >> 5;
    const int lane = threadIdx.x & 31;

#pragma unroll
    for (int p = 0; p < 2; p++) {
        const int row = p * 256 + warp * 32 + lane;
        float* qp = &qo[(size_t)(b * NX + row) * DMODEL + h * DHEAD];

        u64 qv[5], acc[5];
#pragma unroll
        for (int c = 0; c < 5; c++) {
            qv[c]  = *(const u64*)&qp[2 * c];
            acc[c] = 0ULL;
        }
        float ssum = 0.0f;

        for (int ky = 0; ky < NY; ky += 4) {
#pragma unroll
            for (int u = 0; u < 4; u++) {
                const float* krow = &sk[(ky + u) * KPAD];   // broadcast (all lanes same addr)
                const float* vrow = &sv[(ky + u) * KPAD];
                const ulonglong2 k01 = *(const ulonglong2*)(krow);
                const ulonglong2 k23 = *(const ulonglong2*)(krow + 4);
                const u64        k4  = *(const u64*)(krow + 8);
                // dot(q, k) in packed f32x2
                u64 d2;
                d2 = mul2(qv[0], k01.x);
                d2 = ffma2(qv[1], k01.y, d2);
                d2 = ffma2(qv[2], k23.x, d2);
                d2 = ffma2(qv[3], k23.y, d2);
                d2 = ffma2(qv[4], k4,    d2);
                float lo, hi; unpack2(d2, lo, hi);
                const float e = __expf(lo + hi);
                ssum += e;
                const u64 e2 = pack2(e, e);
                const ulonglong2 v01 = *(const ulonglong2*)(vrow);
                const ulonglong2 v23 = *(const ulonglong2*)(vrow + 4);
                const u64        v4  = *(const u64*)(vrow + 8);
                acc[0] = ffma2(e2, v01.x, acc[0]);
                acc[1] = ffma2(e2, v01.y, acc[1]);
                acc[2] = ffma2(e2, v23.x, acc[2]);
                acc[3] = ffma2(e2, v23.y, acc[3]);
                acc[4] = ffma2(e2, v4,    acc[4]);
            }
        }

        const float inv = 1.0f / ssum;
        const u64 inv2 = pack2(inv, inv);
#pragma unroll
        for (int c = 0; c < 5; c++)
            *(u64*)&qp[2 * c] = add2(qv[c], mul2(acc[c], inv2));
    }
}

extern "C" void kernel_launch(void* const* d_in, const int* in_sizes, int n_in,
                              void* d_out, int out_size)
{
    const float* x  = (const float*)d_in[0];
    const float* y  = (const float*)d_in[1];
    const float* Wq = (const float*)d_in[2];
    const float* Wk = (const float*)d_in[3];
    const float* Wv = (const float*)d_in[4];
    float* out = (float*)d_out;

    cudaFuncSetAttribute(attn_kernel, cudaFuncAttributeMaxDynamicSharedMemorySize, ATTN_SMEM);

    proj_kernel<<<768, 256>>>(x, y, Wq, Wk, Wv, out);    // q -> d_out, k/v -> g_k/g_v
    attn_kernel<<<BATCH * NHEAD, 256, ATTN_SMEM>>>(out); // out = q + att, in place
}

// round 7
// speedup vs baseline: 1.9716x; 1.0793x over previous
#include <cuda_runtime.h>

#define BATCH 64
#define NX    512
#define NY    512
#define NHEAD 8
#define DHEAD 10
#define DMODEL 80     // NHEAD*DHEAD
#define KX    768
#define KY    283
#define KY_PAD 288    // ceil(283/16)*16

typedef unsigned long long u64;

// scratch for K/V projections — device globals per harness rules
__device__ float g_k[BATCH * NY * DMODEL];
__device__ float g_v[BATCH * NY * DMODEL];

// ---------------- packed f32x2 helpers ----------------
__device__ __forceinline__ u64 pack2(float lo, float hi) {
    u64 r; asm("mov.b64 %0, {%1, %2};" : "=l"(r) : "f"(lo), "f"(hi)); return r;
}
__device__ __forceinline__ void unpack2(u64 v, float& lo, float& hi) {
    asm("mov.b64 {%0, %1}, %2;" : "=f"(lo), "=f"(hi) : "l"(v));
}
__device__ __forceinline__ u64 ffma2(u64 a, u64 b, u64 c) {
    u64 d; asm("fma.rn.f32x2 %0, %1, %2, %3;" : "=l"(d) : "l"(a), "l"(b), "l"(c)); return d;
}
__device__ __forceinline__ u64 add2(u64 a, u64 b) {
    u64 d; asm("add.rn.f32x2 %0, %1, %2;" : "=l"(d) : "l"(a), "l"(b)); return d;
}
__device__ __forceinline__ u64 mul2(u64 a, u64 b) {
    u64 d; asm("mul.rn.f32x2 %0, %1, %2;" : "=l"(d) : "l"(a), "l"(b)); return d;
}

// ---------------- Generic projection kernel (double-buffered) ----------------
// 768 blocks: [0,256) Q = x@Wq -> out ; [256,512) K = y@Wk -> g_k ; [512,768) V = y@Wv -> g_v
// Block tile: 128 rows x 80 cols, 256 threads, thread tile 4 rows x 10 cols.
__global__ void __launch_bounds__(256) proj_kernel(
    const float* __restrict__ x, const float* __restrict__ y,
    const float* __restrict__ Wq, const float* __restrict__ Wk,
    const float* __restrict__ Wv, float* __restrict__ out)
{
    __shared__ __align__(16) float sx[2][16][132];  // [buf][kk][row]
    __shared__ __align__(16) float sw[2][16 * 80];  // [buf][kk*80 + col]

    const int tid   = threadIdx.x;
    const int ty    = tid >> 3;
    const int tx    = tid & 7;
    const int which = blockIdx.x >> 8;          // 0=Q, 1=K, 2=V
    const int m0    = (blockIdx.x & 255) * 128;

    const float* in = (which == 0) ? x : y;
    const float* W  = (which == 0) ? Wq : ((which == 1) ? Wk : Wv);
    float* dst      = (which == 0) ? out : ((which == 1) ? g_k : g_v);
    const int Kdim  = (which == 0) ? KX : KY;
    const int ntile = ((which == 0) ? KX : KY_PAD) >> 4;

    float4 pfx[2];
    float  pfy[8];
    float  pfw[5];

    auto load_tile = [&](int t) {
        const int k0 = t << 4;
        if (which == 0) {
#pragma unroll
            for (int s = 0; s < 2; s++) {
                const int i = tid + s * 256;
                const int r = i >> 2, q4 = i & 3;
                pfx[s] = *(const float4*)&x[(size_t)(m0 + r) * KX + k0 + q4 * 4];
            }
        } else {
#pragma unroll
            for (int s = 0; s < 8; s++) {
                const int i = tid + s * 256;
                const int r = i >> 4, kk = i & 15;
                const int k = k0 + kk;
                pfy[s] = (k < Kdim) ? in[(size_t)(m0 + r) * Kdim + k] : 0.0f;
            }
        }
#pragma unroll
        for (int s = 0; s < 5; s++) {
            const int i = tid + s * 256;
            const int kk = i / 80, j = i - kk * 80;
            const int k = k0 + kk;
            pfw[s] = (k < Kdim) ? W[(size_t)k * 80 + j] : 0.0f;
        }
    };
    auto store_tile = [&](int buf) {
        if (which == 0) {
#pragma unroll
            for (int s = 0; s < 2; s++) {
                const int i = tid + s * 256;
                const int r = i >> 2, q4 = i & 3;
                sx[buf][q4 * 4 + 0][r] = pfx[s].x;
                sx[buf][q4 * 4 + 1][r] = pfx[s].y;
                sx[buf][q4 * 4 + 2][r] = pfx[s].z;
                sx[buf][q4 * 4 + 3][r] = pfx[s].w;
            }
        } else {
#pragma unroll
            for (int s = 0; s < 8; s++) {
                const int i = tid + s * 256;
                const int r = i >> 4, kk = i & 15;
                sx[buf][kk][r] = pfy[s];
            }
        }
#pragma unroll
        for (int s = 0; s < 5; s++) sw[buf][tid + s * 256] = pfw[s];
    };

    u64 acc[4][5];
#pragma unroll
    for (int r = 0; r < 4; r++)
#pragma unroll
        for (int c = 0; c < 5; c++) acc[r][c] = 0ULL;

    load_tile(0);
    store_tile(0);
    __syncthreads();

    for (int t = 0; t < ntile; t++) {
        const int cur = t & 1;
        const bool more = (t + 1 < ntile);
        if (more) load_tile(t + 1);

#pragma unroll
        for (int kk = 0; kk < 16; kk++) {
            const float4 xv = *(const float4*)&sx[cur][kk][ty * 4];
            const u64* wp = (const u64*)&sw[cur][kk * 80 + tx * 10];
            u64 wd[5];
#pragma unroll
            for (int c = 0; c < 5; c++) wd[c] = wp[c];
            const u64 x0 = pack2(xv.x, xv.x);
            const u64 x1 = pack2(xv.y, xv.y);
            const u64 x2 = pack2(xv.z, xv.z);
            const u64 x3 = pack2(xv.w, xv.w);
#pragma unroll
            for (int c = 0; c < 5; c++) {
                acc[0][c] = ffma2(x0, wd[c], acc[0][c]);
                acc[1][c] = ffma2(x1, wd[c], acc[1][c]);
                acc[2][c] = ffma2(x2, wd[c], acc[2][c]);
                acc[3][c] = ffma2(x3, wd[c], acc[3][c]);
            }
        }

        if (more) store_tile((t + 1) & 1);
        __syncthreads();
    }

#pragma unroll
    for (int j = 0; j < 4; j++) {
        float* o = &dst[(size_t)(m0 + ty * 4 + j) * DMODEL + tx * 10];
#pragma unroll
        for (int c = 0; c < 5; c++) *(u64*)&o[2 * c] = acc[j][c];
    }
}

// ---------------- Attention v3: 2 q-rows per lane, broadcast K/V ----------------
// One block per (b,h). K (pre-scaled) and V staged in smem (KPAD=20, 16B rows).
// Each lane owns TWO q-rows (warp*64+lane and warp*64+32+lane); warp walks all
// 512 keys with broadcast smem reads. One 6-LDS K/V bundle now feeds ~22 FFMA2
// (2 dots + 2 AV updates) -> LDS issue rate is no longer the binding pipe.
// Single pass (8 warps x 32 lanes x 2 rows = 512 rows). No max-subtraction
// (|score| <~ 2), online sum(e) / sum(e*v), out = q + softmax*V in place.
#define KPAD 20
#define ATTN_SMEM (2 * NY * KPAD * 4)

__global__ void __launch_bounds__(256) attn_kernel(float* __restrict__ qo)
{
    extern __shared__ __align__(16) float smem[];
    float* sk = smem;               // NY x KPAD (pre-scaled)
    float* sv = smem + NY * KPAD;

    const int b = blockIdx.x >> 3;
    const int h = blockIdx.x & 7;
    const float scale = 0.31622776601683794f;  // 1/sqrt(10)

    for (int i = threadIdx.x; i < NY * DHEAD; i += 256) {
        const int ky = i / DHEAD, d = i - ky * DHEAD;
        const size_t g = (size_t)(b * NY + ky) * DMODEL + h * DHEAD + d;
        sk[ky * KPAD + d] = g_k[g] * scale;
        sv[ky * KPAD + d] = g_v[g];
    }
    __syncthreads();

    const int warp = threadIdx.x >> 5;
    const int lane = threadIdx.x & 31;

    const int row0 = warp * 64 + lane;
    const int row1 = row0 + 32;
    float* qp0 = &qo[(size_t)(b * NX + row0) * DMODEL + h * DHEAD];
    float* qp1 = &qo[(size_t)(b * NX + row1) * DMODEL + h * DHEAD];

    u64 qv0[5], qv1[5], acc0[5], acc1[5];
#pragma unroll
    for (int c = 0; c < 5; c++) {
        qv0[c] = *(const u64*)&qp0[2 * c];
        qv1[c] = *(const u64*)&qp1[2 * c];
        acc0[c] = 0ULL;
        acc1[c] = 0ULL;
    }
    float ssum0 = 0.0f, ssum1 = 0.0f;

    for (int ky = 0; ky < NY; ky += 4) {
#pragma unroll
        for (int u = 0; u < 4; u++) {
            const float* krow = &sk[(ky + u) * KPAD];   // broadcast (all lanes same addr)
            const float* vrow = &sv[(ky + u) * KPAD];
            const ulonglong2 k01 = *(const ulonglong2*)(krow);
            const ulonglong2 k23 = *(const ulonglong2*)(krow + 4);
            const u64        k4  = *(const u64*)(krow + 8);
            // two dots in parallel (independent chains)
            u64 d0 = mul2(qv0[0], k01.x);
            u64 d1 = mul2(qv1[0], k01.x);
            d0 = ffma2(qv0[1], k01.y, d0);  d1 = ffma2(qv1[1], k01.y, d1);
            d0 = ffma2(qv0[2], k23.x, d0);  d1 = ffma2(qv1[2], k23.x, d1);
            d0 = ffma2(qv0[3], k23.y, d0);  d1 = ffma2(qv1[3], k23.y, d1);
            d0 = ffma2(qv0[4], k4,    d0);  d1 = ffma2(qv1[4], k4,    d1);
            float l0, h0, l1, h1;
            unpack2(d0, l0, h0);
            unpack2(d1, l1, h1);
            const float e0 = __expf(l0 + h0);
            const float e1 = __expf(l1 + h1);
            ssum0 += e0;
            ssum1 += e1;
            const u64 e02 = pack2(e0, e0);
            const u64 e12 = pack2(e1, e1);
            const ulonglong2 v01 = *(const ulonglong2*)(vrow);
            const ulonglong2 v23 = *(const ulonglong2*)(vrow + 4);
            const u64        v4  = *(const u64*)(vrow + 8);
            acc0[0] = ffma2(e02, v01.x, acc0[0]);  acc1[0] = ffma2(e12, v01.x, acc1[0]);
            acc0[1] = ffma2(e02, v01.y, acc0[1]);  acc1[1] = ffma2(e12, v01.y, acc1[1]);
            acc0[2] = ffma2(e02, v23.x, acc0[2]);  acc1[2] = ffma2(e12, v23.x, acc1[2]);
            acc0[3] = ffma2(e02, v23.y, acc0[3]);  acc1[3] = ffma2(e12, v23.y, acc1[3]);
            acc0[4] = ffma2(e02, v4,    acc0[4]);  acc1[4] = ffma2(e12, v4,    acc1[4]);
        }
    }

    const float i0 = 1.0f / ssum0;
    const float i1 = 1.0f / ssum1;
    const u64 i02 = pack2(i0, i0);
    const u64 i12 = pack2(i1, i1);
#pragma unroll
    for (int c = 0; c < 5; c++) {
        *(u64*)&qp0[2 * c] = add2(qv0[c], mul2(acc0[c], i02));
        *(u64*)&qp1[2 * c] = add2(qv1[c], mul2(acc1[c], i12));
    }
}

extern "C" void kernel_launch(void* const* d_in, const int* in_sizes, int n_in,
                              void* d_out, int out_size)
{
    const float* x  = (const float*)d_in[0];
    const float* y  = (const float*)d_in[1];
    const float* Wq = (const float*)d_in[2];
    const float* Wk = (const float*)d_in[3];
    const float* Wv = (const float*)d_in[4];
    float* out = (float*)d_out;

    cudaFuncSetAttribute(attn_kernel, cudaFuncAttributeMaxDynamicSharedMemorySize, ATTN_SMEM);

    proj_kernel<<<768, 256>>>(x, y, Wq, Wk, Wv, out);    // q -> d_out, k/v -> g_k/g_v
    attn_kernel<<<BATCH * NHEAD, 256, ATTN_SMEM>>>(out); // out = q + att, in place
}

// round 8
// speedup vs baseline: 2.0247x; 1.0269x over previous
#include <cuda_runtime.h>

#define BATCH 64
#define NX    512
#define NY    512
#define NHEAD 8
#define DHEAD 10
#define DMODEL 80     // NHEAD*DHEAD
#define KX    768
#define KY    283
#define KY_PAD 288    // ceil(283/16)*16

typedef unsigned long long u64;

// scratch for K/V projections — device globals per harness rules
__device__ float g_k[BATCH * NY * DMODEL];
__device__ float g_v[BATCH * NY * DMODEL];

// ---------------- packed f32x2 helpers ----------------
__device__ __forceinline__ u64 pack2(float lo, float hi) {
    u64 r; asm("mov.b64 %0, {%1, %2};" : "=l"(r) : "f"(lo), "f"(hi)); return r;
}
__device__ __forceinline__ void unpack2(u64 v, float& lo, float& hi) {
    asm("mov.b64 {%0, %1}, %2;" : "=f"(lo), "=f"(hi) : "l"(v));
}
__device__ __forceinline__ u64 ffma2(u64 a, u64 b, u64 c) {
    u64 d; asm("fma.rn.f32x2 %0, %1, %2, %3;" : "=l"(d) : "l"(a), "l"(b), "l"(c)); return d;
}
__device__ __forceinline__ u64 add2(u64 a, u64 b) {
    u64 d; asm("add.rn.f32x2 %0, %1, %2;" : "=l"(d) : "l"(a), "l"(b)); return d;
}
__device__ __forceinline__ u64 mul2(u64 a, u64 b) {
    u64 d; asm("mul.rn.f32x2 %0, %1, %2;" : "=l"(d) : "l"(a), "l"(b)); return d;
}

// ---------------- Generic projection kernel (double-buffered) ----------------
// 768 blocks: [0,256) Q = x@Wq -> out ; [256,512) K = y@Wk -> g_k ; [512,768) V = y@Wv -> g_v
// Block tile: 128 rows x 80 cols, 256 threads, thread tile 4 rows x 10 cols.
__global__ void __launch_bounds__(256) proj_kernel(
    const float* __restrict__ x, const float* __restrict__ y,
    const float* __restrict__ Wq, const float* __restrict__ Wk,
    const float* __restrict__ Wv, float* __restrict__ out)
{
    __shared__ __align__(16) float sx[2][16][132];  // [buf][kk][row]
    __shared__ __align__(16) float sw[2][16 * 80];  // [buf][kk*80 + col]

    const int tid   = threadIdx.x;
    const int ty    = tid >> 3;
    const int tx    = tid & 7;
    const int which = blockIdx.x >> 8;          // 0=Q, 1=K, 2=V
    const int m0    = (blockIdx.x & 255) * 128;

    const float* in = (which == 0) ? x : y;
    const float* W  = (which == 0) ? Wq : ((which == 1) ? Wk : Wv);
    float* dst      = (which == 0) ? out : ((which == 1) ? g_k : g_v);
    const int Kdim  = (which == 0) ? KX : KY;
    const int ntile = ((which == 0) ? KX : KY_PAD) >> 4;

    float4 pfx[2];
    float  pfy[8];
    float  pfw[5];

    auto load_tile = [&](int t) {
        const int k0 = t << 4;
        if (which == 0) {
#pragma unroll
            for (int s = 0; s < 2; s++) {
                const int i = tid + s * 256;
                const int r = i >> 2, q4 = i & 3;
                pfx[s] = *(const float4*)&x[(size_t)(m0 + r) * KX + k0 + q4 * 4];
            }
        } else {
#pragma unroll
            for (int s = 0; s < 8; s++) {
                const int i = tid + s * 256;
                const int r = i >> 4, kk = i & 15;
                const int k = k0 + kk;
                pfy[s] = (k < Kdim) ? in[(size_t)(m0 + r) * Kdim + k] : 0.0f;
            }
        }
#pragma unroll
        for (int s = 0; s < 5; s++) {
            const int i = tid + s * 256;
            const int kk = i / 80, j = i - kk * 80;
            const int k = k0 + kk;
            pfw[s] = (k < Kdim) ? W[(size_t)k * 80 + j] : 0.0f;
        }
    };
    auto store_tile = [&](int buf) {
        if (which == 0) {
#pragma unroll
            for (int s = 0; s < 2; s++) {
                const int i = tid + s * 256;
                const int r = i >> 2, q4 = i & 3;
                sx[buf][q4 * 4 + 0][r] = pfx[s].x;
                sx[buf][q4 * 4 + 1][r] = pfx[s].y;
                sx[buf][q4 * 4 + 2][r] = pfx[s].z;
                sx[buf][q4 * 4 + 3][r] = pfx[s].w;
            }
        } else {
#pragma unroll
            for (int s = 0; s < 8; s++) {
                const int i = tid + s * 256;
                const int r = i >> 4, kk = i & 15;
                sx[buf][kk][r] = pfy[s];
            }
        }
#pragma unroll
        for (int s = 0; s < 5; s++) sw[buf][tid + s * 256] = pfw[s];
    };

    u64 acc[4][5];
#pragma unroll
    for (int r = 0; r < 4; r++)
#pragma unroll
        for (int c = 0; c < 5; c++) acc[r][c] = 0ULL;

    load_tile(0);
    store_tile(0);
    __syncthreads();

    for (int t = 0; t < ntile; t++) {
        const int cur = t & 1;
        const bool more = (t + 1 < ntile);
        if (more) load_tile(t + 1);

#pragma unroll
        for (int kk = 0; kk < 16; kk++) {
            const float4 xv = *(const float4*)&sx[cur][kk][ty * 4];
            const u64* wp = (const u64*)&sw[cur][kk * 80 + tx * 10];
            u64 wd[5];
#pragma unroll
            for (int c = 0; c < 5; c++) wd[c] = wp[c];
            const u64 x0 = pack2(xv.x, xv.x);
            const u64 x1 = pack2(xv.y, xv.y);
            const u64 x2 = pack2(xv.z, xv.z);
            const u64 x3 = pack2(xv.w, xv.w);
#pragma unroll
            for (int c = 0; c < 5; c++) {
                acc[0][c] = ffma2(x0, wd[c], acc[0][c]);
                acc[1][c] = ffma2(x1, wd[c], acc[1][c]);
                acc[2][c] = ffma2(x2, wd[c], acc[2][c]);
                acc[3][c] = ffma2(x3, wd[c], acc[3][c]);
            }
        }

        if (more) store_tile((t + 1) & 1);
        __syncthreads();
    }

#pragma unroll
    for (int j = 0; j < 4; j++) {
        float* o = &dst[(size_t)(m0 + ty * 4 + j) * DMODEL + tx * 10];
#pragma unroll
        for (int c = 0; c < 5; c++) *(u64*)&o[2 * c] = acc[j][c];
    }
}

// ---------------- Attention v4: 2 q-rows per lane, broadcast K/V, high-occ ----------------
// One block per (b,h). K (pre-scaled) and V staged in smem.
// KPAD=12 (48B rows): every row 16B-aligned (48=3*16) -> 2xLDS.128 + 1xLDS.64
// broadcast reads; smem = 48KB/block -> 3 blocks/SM resident (24 warps, occ 37.5%)
// vs 2 blocks at KPAD=20. Each lane owns TWO q-rows; no cross-lane reduction.
// No max-subtraction (|score| <~ 2), online sum(e)/sum(e*v), out = q + softmax*V.
#define KPAD 12
#define ATTN_SMEM (2 * NY * KPAD * 4)

__global__ void __launch_bounds__(256, 3) attn_kernel(float* __restrict__ qo)
{
    extern __shared__ __align__(16) float smem[];
    float* sk = smem;               // NY x KPAD (pre-scaled)
    float* sv = smem + NY * KPAD;   // 24KB offset, 16B-aligned

    const int b = blockIdx.x >> 3;
    const int h = blockIdx.x & 7;
    const float scale = 0.31622776601683794f;  // 1/sqrt(10)

    for (int i = threadIdx.x; i < NY * DHEAD; i += 256) {
        const int ky = i / DHEAD, d = i - ky * DHEAD;
        const size_t g = (size_t)(b * NY + ky) * DMODEL + h * DHEAD + d;
        sk[ky * KPAD + d] = g_k[g] * scale;
        sv[ky * KPAD + d] = g_v[g];
    }
    __syncthreads();

    const int warp = threadIdx.x >> 5;
    const int lane = threadIdx.x & 31;

    const int row0 = warp * 64 + lane;
    const int row1 = row0 + 32;
    float* qp0 = &qo[(size_t)(b * NX + row0) * DMODEL + h * DHEAD];
    float* qp1 = &qo[(size_t)(b * NX + row1) * DMODEL + h * DHEAD];

    u64 qv0[5], qv1[5], acc0[5], acc1[5];
#pragma unroll
    for (int c = 0; c < 5; c++) {
        qv0[c] = *(const u64*)&qp0[2 * c];
        qv1[c] = *(const u64*)&qp1[2 * c];
        acc0[c] = 0ULL;
        acc1[c] = 0ULL;
    }
    float ssum0 = 0.0f, ssum1 = 0.0f;

    for (int ky = 0; ky < NY; ky += 4) {
#pragma unroll
        for (int u = 0; u < 4; u++) {
            const float* krow = &sk[(ky + u) * KPAD];   // broadcast (all lanes same addr)
            const float* vrow = &sv[(ky + u) * KPAD];
            const ulonglong2 k01 = *(const ulonglong2*)(krow);
            const ulonglong2 k23 = *(const ulonglong2*)(krow + 4);
            const u64        k4  = *(const u64*)(krow + 8);
            // two dots in parallel (independent chains)
            u64 d0 = mul2(qv0[0], k01.x);
            u64 d1 = mul2(qv1[0], k01.x);
            d0 = ffma2(qv0[1], k01.y, d0);  d1 = ffma2(qv1[1], k01.y, d1);
            d0 = ffma2(qv0[2], k23.x, d0);  d1 = ffma2(qv1[2], k23.x, d1);
            d0 = ffma2(qv0[3], k23.y, d0);  d1 = ffma2(qv1[3], k23.y, d1);
            d0 = ffma2(qv0[4], k4,    d0);  d1 = ffma2(qv1[4], k4,    d1);
            float l0, h0, l1, h1;
            unpack2(d0, l0, h0);
            unpack2(d1, l1, h1);
            const float e0 = __expf(l0 + h0);
            const float e1 = __expf(l1 + h1);
            ssum0 += e0;
            ssum1 += e1;
            const u64 e02 = pack2(e0, e0);
            const u64 e12 = pack2(e1, e1);
            const ulonglong2 v01 = *(const ulonglong2*)(vrow);
            const ulonglong2 v23 = *(const ulonglong2*)(vrow + 4);
            const u64        v4  = *(const u64*)(vrow + 8);
            acc0[0] = ffma2(e02, v01.x, acc0[0]);  acc1[0] = ffma2(e12, v01.x, acc1[0]);
            acc0[1] = ffma2(e02, v01.y, acc0[1]);  acc1[1] = ffma2(e12, v01.y, acc1[1]);
            acc0[2] = ffma2(e02, v23.x, acc0[2]);  acc1[2] = ffma2(e12, v23.x, acc1[2]);
            acc0[3] = ffma2(e02, v23.y, acc0[3]);  acc1[3] = ffma2(e12, v23.y, acc1[3]);
            acc0[4] = ffma2(e02, v4,    acc0[4]);  acc1[4] = ffma2(e12, v4,    acc1[4]);
        }
    }

    const float i0 = 1.0f / ssum0;
    const float i1 = 1.0f / ssum1;
    const u64 i02 = pack2(i0, i0);
    const u64 i12 = pack2(i1, i1);
#pragma unroll
    for (int c = 0; c < 5; c++) {
        *(u64*)&qp0[2 * c] = add2(qv0[c], mul2(acc0[c], i02));
        *(u64*)&qp1[2 * c] = add2(qv1[c], mul2(acc1[c], i12));
    }
}

extern "C" void kernel_launch(void* const* d_in, const int* in_sizes, int n_in,
                              void* d_out, int out_size)
{
    const float* x  = (const float*)d_in[0];
    const float* y  = (const float*)d_in[1];
    const float* Wq = (const float*)d_in[2];
    const float* Wk = (const float*)d_in[3];
    const float* Wv = (const float*)d_in[4];
    float* out = (float*)d_out;

    cudaFuncSetAttribute(attn_kernel, cudaFuncAttributeMaxDynamicSharedMemorySize, ATTN_SMEM);

    proj_kernel<<<768, 256>>>(x, y, Wq, Wk, Wv, out);    // q -> d_out, k/v -> g_k/g_v
    attn_kernel<<<BATCH * NHEAD, 256, ATTN_SMEM>>>(out); // out = q + att, in place
}

// round 10
// speedup vs baseline: 2.1711x; 1.0723x over previous
#include <cuda_runtime.h>
#include <cstdint>

#define BATCH 64
#define NX    512
#define NY    512
#define NHEAD 8
#define DHEAD 10
#define DMODEL 80     // NHEAD*DHEAD
#define KX    768
#define KY    283
#define KY_PAD 288

typedef unsigned long long u64;

// scratch for K/V projections — device globals per harness rules
__device__ float g_k[BATCH * NY * DMODEL];
__device__ float g_v[BATCH * NY * DMODEL];

// ---------------- packed f32x2 helpers ----------------
__device__ __forceinline__ u64 pack2(float lo, float hi) {
    u64 r; asm("mov.b64 %0, {%1, %2};" : "=l"(r) : "f"(lo), "f"(hi)); return r;
}
__device__ __forceinline__ void unpack2(u64 v, float& lo, float& hi) {
    asm("mov.b64 {%0, %1}, %2;" : "=f"(lo), "=f"(hi) : "l"(v));
}
__device__ __forceinline__ u64 ffma2(u64 a, u64 b, u64 c) {
    u64 d; asm("fma.rn.f32x2 %0, %1, %2, %3;" : "=l"(d) : "l"(a), "l"(b), "l"(c)); return d;
}
__device__ __forceinline__ u64 add2(u64 a, u64 b) {
    u64 d; asm("add.rn.f32x2 %0, %1, %2;" : "=l"(d) : "l"(a), "l"(b)); return d;
}
__device__ __forceinline__ u64 mul2(u64 a, u64 b) {
    u64 d; asm("mul.rn.f32x2 %0, %1, %2;" : "=l"(d) : "l"(a), "l"(b)); return d;
}

// ---------------- tf32 mma helpers (base PTX, works on .target sm_103) ----------------
__device__ __forceinline__ uint32_t f2tf32(float f) {
    uint32_t u; asm("cvt.rna.tf32.f32 %0, %1;" : "=r"(u) : "f"(f)); return u;
}
__device__ __forceinline__ void mma_tf32(float c[4], const uint32_t a[4],
                                         uint32_t b0, uint32_t b1) {
    asm volatile(
        "mma.sync.aligned.m16n8k8.row.col.f32.tf32.tf32.f32 "
        "{%0,%1,%2,%3}, {%4,%5,%6,%7}, {%8,%9}, {%0,%1,%2,%3};"
        : "+f"(c[0]), "+f"(c[1]), "+f"(c[2]), "+f"(c[3])
        : "r"(a[0]), "r"(a[1]), "r"(a[2]), "r"(a[3]), "r"(b0), "r"(b1));
}

// ---------------- Projection via mma.sync tf32 ----------------
// 768 CTAs x 256 thr (8 warps): [0,256) Q (3-term compensated) ; [256,512) K ; [512,768) V.
// Block tile 128 rows x 80 cols; warp tile m16 x n80 (10 n8 tiles); K chunk = 16 (2 k8 steps).
// Smem (u32 units, padded strides for conflict-free frag loads):
//   A hi: [2][16][136]  A lo (Q only): [2][16][136]  B hi: [2][16][88]  B lo (Q): [2][16][88]
#define SXH_OFF 0
#define SXL_OFF 4352            // 2*16*136
#define SWH_OFF 8704
#define SWL_OFF 11520           // + 2*16*88
#define PJ_SMEM_U32 14336
#define PJ_SMEM_BYTES (PJ_SMEM_U32 * 4)

__global__ void __launch_bounds__(256) proj_mma_kernel(
    const float* __restrict__ x, const float* __restrict__ y,
    const float* __restrict__ Wq, const float* __restrict__ Wk,
    const float* __restrict__ Wv, float* __restrict__ out)
{
    extern __shared__ __align__(16) uint32_t su[];
    uint32_t* sxh = su + SXH_OFF;
    uint32_t* sxl = su + SXL_OFF;
    uint32_t* swh = su + SWH_OFF;
    uint32_t* swl = su + SWL_OFF;

    const int tid   = threadIdx.x;
    const int warp  = tid >> 5;
    const int lane  = tid & 31;
    const int g     = lane >> 2;       // 0..7
    const int tig   = lane & 3;        // 0..3
    const int which = blockIdx.x >> 8; // 0=Q, 1=K, 2=V
    const bool isQ  = (which == 0);
    const int m0    = (blockIdx.x & 255) * 128;

    const float* W = isQ ? Wq : ((which == 1) ? Wk : Wv);
    float* dst     = isQ ? out : ((which == 1) ? g_k : g_v);
    const int Kdim = isQ ? KX : KY;
    const int ntile = (isQ ? KX : KY_PAD) >> 4;   // 48 or 18

    float4 pfx[2];   // Q: x prefetch (aligned float4)
    float  pfy[8];   // KV: y prefetch (scalar guarded)
    float  pfw[5];   // W prefetch

    auto load_tile = [&](int t) {
        const int k0 = t << 4;
        if (isQ) {
#pragma unroll
            for (int s = 0; s < 2; s++) {
                const int i = tid + s * 256;
                const int r = i >> 2, q4 = i & 3;
                pfx[s] = *(const float4*)&x[(size_t)(m0 + r) * KX + k0 + q4 * 4];
            }
        } else {
#pragma unroll
            for (int s = 0; s < 8; s++) {
                const int i = tid + s * 256;
                const int r = i >> 4, kk = i & 15;
                const int k = k0 + kk;
                pfy[s] = (k < Kdim) ? y[(size_t)(m0 + r) * KY + k] : 0.0f;
            }
        }
#pragma unroll
        for (int s = 0; s < 5; s++) {
            const int i = tid + s * 256;
            const int kk = i / 80, j = i - kk * 80;
            const int k = k0 + kk;
            pfw[s] = (k < Kdim) ? W[(size_t)k * 80 + j] : 0.0f;
        }
    };
    auto store_tile = [&](int buf) {
        if (isQ) {
#pragma unroll
            for (int s = 0; s < 2; s++) {
                const int i = tid + s * 256;
                const int r = i >> 2, q4 = i & 3;
                const float v[4] = { pfx[s].x, pfx[s].y, pfx[s].z, pfx[s].w };
#pragma unroll
                for (int j = 0; j < 4; j++) {
                    const uint32_t h = f2tf32(v[j]);
                    const float lo = v[j] - __uint_as_float(h);
                    const int a = buf * 2176 + (q4 * 4 + j) * 136 + r;
                    sxh[a] = h;
                    sxl[a] = f2tf32(lo);
                }
            }
        } else {
#pragma unroll
            for (int s = 0; s < 8; s++) {
                const int i = tid + s * 256;
                const int r = i >> 4, kk = i & 15;
                sxh[buf * 2176 + kk * 136 + r] = f2tf32(pfy[s]);
            }
        }
#pragma unroll
        for (int s = 0; s < 5; s++) {
            const int i = tid + s * 256;
            const int kk = i / 80, j = i - kk * 80;
            const uint32_t h = f2tf32(pfw[s]);
            const int a = buf * 1408 + kk * 88 + j;
            swh[a] = h;
            if (isQ) swl[a] = f2tf32(pfw[s] - __uint_as_float(h));
        }
    };

    float c[10][4];
#pragma unroll
    for (int n = 0; n < 10; n++)
#pragma unroll
        for (int j = 0; j < 4; j++) c[n][j] = 0.0f;

    load_tile(0);
    store_tile(0);
    __syncthreads();

    const int arow = warp * 16 + g;

    for (int t = 0; t < ntile; t++) {
        const int cur = t & 1;
        const bool more = (t + 1 < ntile);
        if (more) load_tile(t + 1);

        const uint32_t* SXH = sxh + cur * 2176;
        const uint32_t* SXL = sxl + cur * 2176;
        const uint32_t* SWH = swh + cur * 1408;
        const uint32_t* SWL = swl + cur * 1408;

#pragma unroll
        for (int k8 = 0; k8 < 2; k8++) {
            const int kb = k8 * 8;
            // A fragment (m16k8 row-major): a0:(g,tig) a1:(g+8,tig) a2:(g,tig+4) a3:(g+8,tig+4)
            uint32_t ah[4], al[4];
            ah[0] = SXH[(kb + tig) * 136 + arow];
            ah[1] = SXH[(kb + tig) * 136 + arow + 8];
            ah[2] = SXH[(kb + tig + 4) * 136 + arow];
            ah[3] = SXH[(kb + tig + 4) * 136 + arow + 8];
            if (isQ) {
                al[0] = SXL[(kb + tig) * 136 + arow];
                al[1] = SXL[(kb + tig) * 136 + arow + 8];
                al[2] = SXL[(kb + tig + 4) * 136 + arow];
                al[3] = SXL[(kb + tig + 4) * 136 + arow + 8];
            }
#pragma unroll
            for (int n = 0; n < 10; n++) {
                // B fragment (n8k8 col layout): b0:(k=tig, n=g) b1:(k=tig+4, n=g)
                const uint32_t b0 = SWH[(kb + tig) * 88 + n * 8 + g];
                const uint32_t b1 = SWH[(kb + tig + 4) * 88 + n * 8 + g];
                mma_tf32(c[n], ah, b0, b1);
                if (isQ) {
                    mma_tf32(c[n], al, b0, b1);    // xl * Wh
                    const uint32_t l0 = SWL[(kb + tig) * 88 + n * 8 + g];
                    const uint32_t l1 = SWL[(kb + tig + 4) * 88 + n * 8 + g];
                    mma_tf32(c[n], ah, l0, l1);    // xh * Wl
                }
            }
        }

        if (more) store_tile((t + 1) & 1);
        __syncthreads();
    }

    // writeout: c[n] -> rows m0+warp*16+g and +8, cols n*8 + 2*tig, +1
    float* o0 = &dst[(size_t)(m0 + warp * 16 + g) * DMODEL];
    float* o1 = o0 + (size_t)8 * DMODEL;
#pragma unroll
    for (int n = 0; n < 10; n++) {
        *(float2*)&o0[n * 8 + 2 * tig] = make_float2(c[n][0], c[n][1]);
        *(float2*)&o1[n * 8 + 2 * tig] = make_float2(c[n][2], c[n][3]);
    }
}

// ---------------- Attention v4: 2 q-rows per lane, broadcast K/V, high-occ ----------------
// (unchanged from R8 — 161us)
#define KPAD 12
#define ATTN_SMEM (2 * NY * KPAD * 4)

__global__ void __launch_bounds__(256, 3) attn_kernel(float* __restrict__ qo)
{
    extern __shared__ __align__(16) float fsmem[];
    float* sk = fsmem;               // NY x KPAD (pre-scaled)
    float* sv = fsmem + NY * KPAD;

    const int b = blockIdx.x >> 3;
    const int h = blockIdx.x & 7;
    const float scale = 0.31622776601683794f;  // 1/sqrt(10)

    for (int i = threadIdx.x; i < NY * DHEAD; i += 256) {
        const int ky = i / DHEAD, d = i - ky * DHEAD;
        const size_t g = (size_t)(b * NY + ky) * DMODEL + h * DHEAD + d;
        sk[ky * KPAD + d] = g_k[g] * scale;
        sv[ky * KPAD + d] = g_v[g];
    }
    __syncthreads();

    const int warp = threadIdx.x >> 5;
    const int lane = threadIdx.x & 31;

    const int row0 = warp * 64 + lane;
    const int row1 = row0 + 32;
    float* qp0 = &qo[(size_t)(b * NX + row0) * DMODEL + h * DHEAD];
    float* qp1 = &qo[(size_t)(b * NX + row1) * DMODEL + h * DHEAD];

    u64 qv0[5], qv1[5], acc0[5], acc1[5];
#pragma unroll
    for (int c = 0; c < 5; c++) {
        qv0[c] = *(const u64*)&qp0[2 * c];
        qv1[c] = *(const u64*)&qp1[2 * c];
        acc0[c] = 0ULL;
        acc1[c] = 0ULL;
    }
    float ssum0 = 0.0f, ssum1 = 0.0f;

    for (int ky = 0; ky < NY; ky += 4) {
#pragma unroll
        for (int u = 0; u < 4; u++) {
            const float* krow = &sk[(ky + u) * KPAD];   // broadcast (all lanes same addr)
            const float* vrow = &sv[(ky + u) * KPAD];
            const ulonglong2 k01 = *(const ulonglong2*)(krow);
            const ulonglong2 k23 = *(const ulonglong2*)(krow + 4);
            const u64        k4  = *(const u64*)(krow + 8);
            u64 d0 = mul2(qv0[0], k01.x);
            u64 d1 = mul2(qv1[0], k01.x);
            d0 = ffma2(qv0[1], k01.y, d0);  d1 = ffma2(qv1[1], k01.y, d1);
            d0 = ffma2(qv0[2], k23.x, d0);  d1 = ffma2(qv1[2], k23.x, d1);
            d0 = ffma2(qv0[3], k23.y, d0);  d1 = ffma2(qv1[3], k23.y, d1);
            d0 = ffma2(qv0[4], k4,    d0);  d1 = ffma2(qv1[4], k4,    d1);
            float l0, h0, l1, h1;
            unpack2(d0, l0, h0);
            unpack2(d1, l1, h1);
            const float e0 = __expf(l0 + h0);
            const float e1 = __expf(l1 + h1);
            ssum0 += e0;
            ssum1 += e1;
            const u64 e02 = pack2(e0, e0);
            const u64 e12 = pack2(e1, e1);
            const ulonglong2 v01 = *(const ulonglong2*)(vrow);
            const ulonglong2 v23 = *(const ulonglong2*)(vrow + 4);
            const u64        v4  = *(const u64*)(vrow + 8);
            acc0[0] = ffma2(e02, v01.x, acc0[0]);  acc1[0] = ffma2(e12, v01.x, acc1[0]);
            acc0[1] = ffma2(e02, v01.y, acc0[1]);  acc1[1] = ffma2(e12, v01.y, acc1[1]);
            acc0[2] = ffma2(e02, v23.x, acc0[2]);  acc1[2] = ffma2(e12, v23.x, acc1[2]);
            acc0[3] = ffma2(e02, v23.y, acc0[3]);  acc1[3] = ffma2(e12, v23.y, acc1[3]);
            acc0[4] = ffma2(e02, v4,    acc0[4]);  acc1[4] = ffma2(e12, v4,    acc1[4]);
        }
    }

    const float i0 = 1.0f / ssum0;
    const float i1 = 1.0f / ssum1;
    const u64 i02 = pack2(i0, i0);
    const u64 i12 = pack2(i1, i1);
#pragma unroll
    for (int c = 0; c < 5; c++) {
        *(u64*)&qp0[2 * c] = add2(qv0[c], mul2(acc0[c], i02));
        *(u64*)&qp1[2 * c] = add2(qv1[c], mul2(acc1[c], i12));
    }
}

extern "C" void kernel_launch(void* const* d_in, const int* in_sizes, int n_in,
                              void* d_out, int out_size)
{
    const float* x  = (const float*)d_in[0];
    const float* y  = (const float*)d_in[1];
    const float* Wq = (const float*)d_in[2];
    const float* Wk = (const float*)d_in[3];
    const float* Wv = (const float*)d_in[4];
    float* out = (float*)d_out;

    cudaFuncSetAttribute(proj_mma_kernel, cudaFuncAttributeMaxDynamicSharedMemorySize, PJ_SMEM_BYTES);
    cudaFuncSetAttribute(attn_kernel, cudaFuncAttributeMaxDynamicSharedMemorySize, ATTN_SMEM);

    proj_mma_kernel<<<768, 256, PJ_SMEM_BYTES>>>(x, y, Wq, Wk, Wv, out);
    attn_kernel<<<BATCH * NHEAD, 256, ATTN_SMEM>>>(out);  // out = q + att, in place
}

// round 11
// speedup vs baseline: 2.2317x; 1.0280x over previous
#include <cuda_runtime.h>
#include <cstdint>

#define BATCH 64
#define NX    512
#define NY    512
#define NHEAD 8
#define DHEAD 10
#define DMODEL 80     // NHEAD*DHEAD
#define KX    768
#define KY    283
#define KY_PAD 288

typedef unsigned long long u64;

// scratch for K/V projections — device globals per harness rules
__device__ float g_k[BATCH * NY * DMODEL];
__device__ float g_v[BATCH * NY * DMODEL];

// ---------------- packed f32x2 helpers ----------------
__device__ __forceinline__ u64 pack2(float lo, float hi) {
    u64 r; asm("mov.b64 %0, {%1, %2};" : "=l"(r) : "f"(lo), "f"(hi)); return r;
}
__device__ __forceinline__ void unpack2(u64 v, float& lo, float& hi) {
    asm("mov.b64 {%0, %1}, %2;" : "=f"(lo), "=f"(hi) : "l"(v));
}
__device__ __forceinline__ u64 ffma2(u64 a, u64 b, u64 c) {
    u64 d; asm("fma.rn.f32x2 %0, %1, %2, %3;" : "=l"(d) : "l"(a), "l"(b), "l"(c)); return d;
}
__device__ __forceinline__ u64 add2(u64 a, u64 b) {
    u64 d; asm("add.rn.f32x2 %0, %1, %2;" : "=l"(d) : "l"(a), "l"(b)); return d;
}
__device__ __forceinline__ u64 mul2(u64 a, u64 b) {
    u64 d; asm("mul.rn.f32x2 %0, %1, %2;" : "=l"(d) : "l"(a), "l"(b)); return d;
}

// ---------------- tf32 mma helpers (base PTX, works on .target sm_103) ----------------
__device__ __forceinline__ uint32_t f2tf32(float f) {
    uint32_t u; asm("cvt.rna.tf32.f32 %0, %1;" : "=r"(u) : "f"(f)); return u;
}
__device__ __forceinline__ void mma_tf32(float c[4], const uint32_t a[4],
                                         uint32_t b0, uint32_t b1) {
    asm volatile(
        "mma.sync.aligned.m16n8k8.row.col.f32.tf32.tf32.f32 "
        "{%0,%1,%2,%3}, {%4,%5,%6,%7}, {%8,%9}, {%0,%1,%2,%3};"
        : "+f"(c[0]), "+f"(c[1]), "+f"(c[2]), "+f"(c[3])
        : "r"(a[0]), "r"(a[1]), "r"(a[2]), "r"(a[3]), "r"(b0), "r"(b1));
}

// ---------------- Projection via mma.sync tf32 (2-term compensated Q) ----------------
// 768 CTAs x 256 thr (8 warps): [0,256) Q = (xh+xl)@tf32(Wq) ; [256,512) K ; [512,768) V.
// Block tile 128 rows x 80 cols; warp tile m16 x n80; K chunk = 16 (2 k8 steps).
// Smem (u32 units, padded strides): A hi [2][16][136], A lo (Q) [2][16][136], B [2][16][88].
#define SXH_OFF 0
#define SXL_OFF 4352            // 2*16*136
#define SWH_OFF 8704
#define PJ_SMEM_U32 11520       // + 2*16*88
#define PJ_SMEM_BYTES (PJ_SMEM_U32 * 4)

__global__ void __launch_bounds__(256) proj_mma_kernel(
    const float* __restrict__ x, const float* __restrict__ y,
    const float* __restrict__ Wq, const float* __restrict__ Wk,
    const float* __restrict__ Wv, float* __restrict__ out)
{
    extern __shared__ __align__(16) uint32_t su[];
    uint32_t* sxh = su + SXH_OFF;
    uint32_t* sxl = su + SXL_OFF;
    uint32_t* swh = su + SWH_OFF;

    const int tid   = threadIdx.x;
    const int warp  = tid >> 5;
    const int lane  = tid & 31;
    const int g     = lane >> 2;       // 0..7
    const int tig   = lane & 3;        // 0..3
    const int which = blockIdx.x >> 8; // 0=Q, 1=K, 2=V
    const bool isQ  = (which == 0);
    const int m0    = (blockIdx.x & 255) * 128;

    const float* W = isQ ? Wq : ((which == 1) ? Wk : Wv);
    float* dst     = isQ ? out : ((which == 1) ? g_k : g_v);
    const int Kdim = isQ ? KX : KY;
    const int ntile = (isQ ? KX : KY_PAD) >> 4;   // 48 or 18

    float4 pfx[2];   // Q: x prefetch (aligned float4)
    float  pfy[8];   // KV: y prefetch (scalar guarded)
    float  pfw[5];   // W prefetch

    auto load_tile = [&](int t) {
        const int k0 = t << 4;
        if (isQ) {
#pragma unroll
            for (int s = 0; s < 2; s++) {
                const int i = tid + s * 256;
                const int r = i >> 2, q4 = i & 3;
                pfx[s] = *(const float4*)&x[(size_t)(m0 + r) * KX + k0 + q4 * 4];
            }
        } else {
#pragma unroll
            for (int s = 0; s < 8; s++) {
                const int i = tid + s * 256;
                const int r = i >> 4, kk = i & 15;
                const int k = k0 + kk;
                pfy[s] = (k < Kdim) ? y[(size_t)(m0 + r) * KY + k] : 0.0f;
            }
        }
#pragma unroll
        for (int s = 0; s < 5; s++) {
            const int i = tid + s * 256;
            const int kk = i / 80, j = i - kk * 80;
            const int k = k0 + kk;
            pfw[s] = (k < Kdim) ? W[(size_t)k * 80 + j] : 0.0f;
        }
    };
    auto store_tile = [&](int buf) {
        if (isQ) {
#pragma unroll
            for (int s = 0; s < 2; s++) {
                const int i = tid + s * 256;
                const int r = i >> 2, q4 = i & 3;
                const float v[4] = { pfx[s].x, pfx[s].y, pfx[s].z, pfx[s].w };
#pragma unroll
                for (int j = 0; j < 4; j++) {
                    const uint32_t h = f2tf32(v[j]);
                    const float lo = v[j] - __uint_as_float(h);
                    const int a = buf * 2176 + (q4 * 4 + j) * 136 + r;
                    sxh[a] = h;
                    sxl[a] = f2tf32(lo);
                }
            }
        } else {
#pragma unroll
            for (int s = 0; s < 8; s++) {
                const int i = tid + s * 256;
                const int r = i >> 4, kk = i & 15;
                sxh[buf * 2176 + kk * 136 + r] = f2tf32(pfy[s]);
            }
        }
#pragma unroll
        for (int s = 0; s < 5; s++) {
            const int i = tid + s * 256;
            const int kk = i / 80, j = i - kk * 80;
            swh[buf * 1408 + kk * 88 + j] = f2tf32(pfw[s]);
        }
    };

    float c[10][4];
#pragma unroll
    for (int n = 0; n < 10; n++)
#pragma unroll
        for (int j = 0; j < 4; j++) c[n][j] = 0.0f;

    load_tile(0);
    store_tile(0);
    __syncthreads();

    const int arow = warp * 16 + g;

    for (int t = 0; t < ntile; t++) {
        const int cur = t & 1;
        const bool more = (t + 1 < ntile);
        if (more) load_tile(t + 1);

        const uint32_t* SXH = sxh + cur * 2176;
        const uint32_t* SXL = sxl + cur * 2176;
        const uint32_t* SWH = swh + cur * 1408;

#pragma unroll
        for (int k8 = 0; k8 < 2; k8++) {
            const int kb = k8 * 8;
            uint32_t ah[4], al[4];
            ah[0] = SXH[(kb + tig) * 136 + arow];
            ah[1] = SXH[(kb + tig) * 136 + arow + 8];
            ah[2] = SXH[(kb + tig + 4) * 136 + arow];
            ah[3] = SXH[(kb + tig + 4) * 136 + arow + 8];
            if (isQ) {
                al[0] = SXL[(kb + tig) * 136 + arow];
                al[1] = SXL[(kb + tig) * 136 + arow + 8];
                al[2] = SXL[(kb + tig + 4) * 136 + arow];
                al[3] = SXL[(kb + tig + 4) * 136 + arow + 8];
            }
#pragma unroll
            for (int n = 0; n < 10; n++) {
                const uint32_t b0 = SWH[(kb + tig) * 88 + n * 8 + g];
                const uint32_t b1 = SWH[(kb + tig + 4) * 88 + n * 8 + g];
                mma_tf32(c[n], ah, b0, b1);
                if (isQ) mma_tf32(c[n], al, b0, b1);   // xl * Wh compensation
            }
        }

        if (more) store_tile((t + 1) & 1);
        __syncthreads();
    }

    float* o0 = &dst[(size_t)(m0 + warp * 16 + g) * DMODEL];
    float* o1 = o0 + (size_t)8 * DMODEL;
#pragma unroll
    for (int n = 0; n < 10; n++) {
        *(float2*)&o0[n * 8 + 2 * tig] = make_float2(c[n][0], c[n][1]);
        *(float2*)&o1[n * 8 + 2 * tig] = make_float2(c[n][2], c[n][3]);
    }
}

// ---------------- Attention v5: 1 q-row per lane, broadcast K/V, occ 50% ----------------
// One block per (b,h). KPAD=12 (48KB smem) + ~52 regs -> 4 blocks/SM (32 warps).
// Each lane owns ONE q-row; 2 passes (8 warps x 32 lanes x 2 = 512 rows).
// K pre-scaled by (1/sqrt(dk))*log2(e); e = ex2.approx(score) -> saves the expf mul.
// No max-subtraction (|score| <~ 2), online sum(e)/sum(e*v), out = q + softmax*V.
#define KPAD 12
#define ATTN_SMEM (2 * NY * KPAD * 4)

__global__ void __launch_bounds__(256, 4) attn_kernel(float* __restrict__ qo)
{
    extern __shared__ __align__(16) float fsmem[];
    float* sk = fsmem;               // NY x KPAD (pre-scaled by scale*log2e)
    float* sv = fsmem + NY * KPAD;

    const int b = blockIdx.x >> 3;
    const int h = blockIdx.x & 7;
    const float scale = 0.31622776601683794f * 1.4426950408889634f;  // 1/sqrt(10) * log2(e)

    for (int i = threadIdx.x; i < NY * DHEAD; i += 256) {
        const int ky = i / DHEAD, d = i - ky * DHEAD;
        const size_t g = (size_t)(b * NY + ky) * DMODEL + h * DHEAD + d;
        sk[ky * KPAD + d] = g_k[g] * scale;
        sv[ky * KPAD + d] = g_v[g];
    }
    __syncthreads();

#pragma unroll
    for (int p = 0; p < 2; p++) {
        const int row = p * 256 + threadIdx.x;
        float* qp = &qo[(size_t)(b * NX + row) * DMODEL + h * DHEAD];

        u64 qv[5], acc[5];
#pragma unroll
        for (int c = 0; c < 5; c++) {
            qv[c]  = *(const u64*)&qp[2 * c];
            acc[c] = 0ULL;
        }
        float ssum = 0.0f;

        for (int ky = 0; ky < NY; ky += 4) {
#pragma unroll
            for (int u = 0; u < 4; u++) {
                const float* krow = &sk[(ky + u) * KPAD];   // broadcast
                const float* vrow = &sv[(ky + u) * KPAD];
                const ulonglong2 k01 = *(const ulonglong2*)(krow);
                const ulonglong2 k23 = *(const ulonglong2*)(krow + 4);
                const u64        k4  = *(const u64*)(krow + 8);
                u64 d2 = mul2(qv[0], k01.x);
                d2 = ffma2(qv[1], k01.y, d2);
                d2 = ffma2(qv[2], k23.x, d2);
                d2 = ffma2(qv[3], k23.y, d2);
                d2 = ffma2(qv[4], k4,    d2);
                float lo, hi; unpack2(d2, lo, hi);
                float e;
                asm("ex2.approx.f32 %0, %1;" : "=f"(e) : "f"(lo + hi));
                ssum += e;
                const u64 e2 = pack2(e, e);
                const ulonglong2 v01 = *(const ulonglong2*)(vrow);
                const ulonglong2 v23 = *(const ulonglong2*)(vrow + 4);
                const u64        v4  = *(const u64*)(vrow + 8);
                acc[0] = ffma2(e2, v01.x, acc[0]);
                acc[1] = ffma2(e2, v01.y, acc[1]);
                acc[2] = ffma2(e2, v23.x, acc[2]);
                acc[3] = ffma2(e2, v23.y, acc[3]);
                acc[4] = ffma2(e2, v4,    acc[4]);
            }
        }

        const float inv = 1.0f / ssum;
        const u64 inv2 = pack2(inv, inv);
#pragma unroll
        for (int c = 0; c < 5; c++)
            *(u64*)&qp[2 * c] = add2(qv[c], mul2(acc[c], inv2));
    }
}

extern "C" void kernel_launch(void* const* d_in, const int* in_sizes, int n_in,
                              void* d_out, int out_size)
{
    const float* x  = (const float*)d_in[0];
    const float* y  = (const float*)d_in[1];
    const float* Wq = (const float*)d_in[2];
    const float* Wk = (const float*)d_in[3];
    const float* Wv = (const float*)d_in[4];
    float* out = (float*)d_out;

    cudaFuncSetAttribute(proj_mma_kernel, cudaFuncAttributeMaxDynamicSharedMemorySize, PJ_SMEM_BYTES);
    cudaFuncSetAttribute(attn_kernel, cudaFuncAttributeMaxDynamicSharedMemorySize, ATTN_SMEM);

    proj_mma_kernel<<<768, 256, PJ_SMEM_BYTES>>>(x, y, Wq, Wk, Wv, out);
    attn_kernel<<<BATCH * NHEAD, 256, ATTN_SMEM>>>(out);  // out = q + att, in place
}

// round 12
// speedup vs baseline: 2.4537x; 1.0995x over previous
#include <cuda_runtime.h>
#include <cstdint>

#define BATCH 64
#define NX    512
#define NY    512
#define NHEAD 8
#define DHEAD 10
#define DMODEL 80     // NHEAD*DHEAD
#define KX    768
#define KY    283
#define KY_PAD 288

typedef unsigned long long u64;

// scratch for K/V projections — device globals per harness rules
__device__ float g_k[BATCH * NY * DMODEL];
__device__ float g_v[BATCH * NY * DMODEL];

// ---------------- packed f32x2 helpers ----------------
__device__ __forceinline__ u64 pack2(float lo, float hi) {
    u64 r; asm("mov.b64 %0, {%1, %2};" : "=l"(r) : "f"(lo), "f"(hi)); return r;
}
__device__ __forceinline__ void unpack2(u64 v, float& lo, float& hi) {
    asm("mov.b64 {%0, %1}, %2;" : "=f"(lo), "=f"(hi) : "l"(v));
}
__device__ __forceinline__ u64 ffma2(u64 a, u64 b, u64 c) {
    u64 d; asm("fma.rn.f32x2 %0, %1, %2, %3;" : "=l"(d) : "l"(a), "l"(b), "l"(c)); return d;
}
__device__ __forceinline__ u64 add2(u64 a, u64 b) {
    u64 d; asm("add.rn.f32x2 %0, %1, %2;" : "=l"(d) : "l"(a), "l"(b)); return d;
}
__device__ __forceinline__ u64 mul2(u64 a, u64 b) {
    u64 d; asm("mul.rn.f32x2 %0, %1, %2;" : "=l"(d) : "l"(a), "l"(b)); return d;
}

// ---------------- tf32 mma helpers (base PTX, works on .target sm_103) ----------------
__device__ __forceinline__ uint32_t f2tf32(float f) {
    uint32_t u; asm("cvt.rna.tf32.f32 %0, %1;" : "=r"(u) : "f"(f)); return u;
}
__device__ __forceinline__ void mma_tf32(float c[4], const uint32_t a[4],
                                         uint32_t b0, uint32_t b1) {
    asm volatile(
        "mma.sync.aligned.m16n8k8.row.col.f32.tf32.tf32.f32 "
        "{%0,%1,%2,%3}, {%4,%5,%6,%7}, {%8,%9}, {%0,%1,%2,%3};"
        : "+f"(c[0]), "+f"(c[1]), "+f"(c[2]), "+f"(c[3])
        : "r"(a[0]), "r"(a[1]), "r"(a[2]), "r"(a[3]), "r"(b0), "r"(b1));
}

// ---------------- Projection via mma.sync tf32 (2-term compensated Q) ----------------
// 768 CTAs x 256 thr (8 warps): [0,256) Q = (xh+xl)@tf32(Wq) ; [256,512) K ; [512,768) V.
// Block tile 128 rows x 80 cols; warp tile m16 x n80; K chunk = 16 (2 k8 steps).
#define SXH_OFF 0
#define SXL_OFF 4352            // 2*16*136
#define SWH_OFF 8704
#define PJ_SMEM_U32 11520       // + 2*16*88
#define PJ_SMEM_BYTES (PJ_SMEM_U32 * 4)

__global__ void __launch_bounds__(256) proj_mma_kernel(
    const float* __restrict__ x, const float* __restrict__ y,
    const float* __restrict__ Wq, const float* __restrict__ Wk,
    const float* __restrict__ Wv, float* __restrict__ out)
{
    extern __shared__ __align__(16) uint32_t su[];
    uint32_t* sxh = su + SXH_OFF;
    uint32_t* sxl = su + SXL_OFF;
    uint32_t* swh = su + SWH_OFF;

    const int tid   = threadIdx.x;
    const int warp  = tid >> 5;
    const int lane  = tid & 31;
    const int g     = lane >> 2;       // 0..7
    const int tig   = lane & 3;        // 0..3
    const int which = blockIdx.x >> 8; // 0=Q, 1=K, 2=V
    const bool isQ  = (which == 0);
    const int m0    = (blockIdx.x & 255) * 128;

    const float* W = isQ ? Wq : ((which == 1) ? Wk : Wv);
    float* dst     = isQ ? out : ((which == 1) ? g_k : g_v);
    const int Kdim = isQ ? KX : KY;
    const int ntile = (isQ ? KX : KY_PAD) >> 4;   // 48 or 18

    float4 pfx[2];
    float  pfy[8];
    float  pfw[5];

    auto load_tile = [&](int t) {
        const int k0 = t << 4;
        if (isQ) {
#pragma unroll
            for (int s = 0; s < 2; s++) {
                const int i = tid + s * 256;
                const int r = i >> 2, q4 = i & 3;
                pfx[s] = *(const float4*)&x[(size_t)(m0 + r) * KX + k0 + q4 * 4];
            }
        } else {
#pragma unroll
            for (int s = 0; s < 8; s++) {
                const int i = tid + s * 256;
                const int r = i >> 4, kk = i & 15;
                const int k = k0 + kk;
                pfy[s] = (k < Kdim) ? y[(size_t)(m0 + r) * KY + k] : 0.0f;
            }
        }
#pragma unroll
        for (int s = 0; s < 5; s++) {
            const int i = tid + s * 256;
            const int kk = i / 80, j = i - kk * 80;
            const int k = k0 + kk;
            pfw[s] = (k < Kdim) ? W[(size_t)k * 80 + j] : 0.0f;
        }
    };
    auto store_tile = [&](int buf) {
        if (isQ) {
#pragma unroll
            for (int s = 0; s < 2; s++) {
                const int i = tid + s * 256;
                const int r = i >> 2, q4 = i & 3;
                const float v[4] = { pfx[s].x, pfx[s].y, pfx[s].z, pfx[s].w };
#pragma unroll
                for (int j = 0; j < 4; j++) {
                    const uint32_t h = f2tf32(v[j]);
                    const float lo = v[j] - __uint_as_float(h);
                    const int a = buf * 2176 + (q4 * 4 + j) * 136 + r;
                    sxh[a] = h;
                    sxl[a] = f2tf32(lo);
                }
            }
        } else {
#pragma unroll
            for (int s = 0; s < 8; s++) {
                const int i = tid + s * 256;
                const int r = i >> 4, kk = i & 15;
                sxh[buf * 2176 + kk * 136 + r] = f2tf32(pfy[s]);
            }
        }
#pragma unroll
        for (int s = 0; s < 5; s++) {
            const int i = tid + s * 256;
            const int kk = i / 80, j = i - kk * 80;
            swh[buf * 1408 + kk * 88 + j] = f2tf32(pfw[s]);
        }
    };

    float c[10][4];
#pragma unroll
    for (int n = 0; n < 10; n++)
#pragma unroll
        for (int j = 0; j < 4; j++) c[n][j] = 0.0f;

    load_tile(0);
    store_tile(0);
    __syncthreads();

    const int arow = warp * 16 + g;

    for (int t = 0; t < ntile; t++) {
        const int cur = t & 1;
        const bool more = (t + 1 < ntile);
        if (more) load_tile(t + 1);

        const uint32_t* SXH = sxh + cur * 2176;
        const uint32_t* SXL = sxl + cur * 2176;
        const uint32_t* SWH = swh + cur * 1408;

#pragma unroll
        for (int k8 = 0; k8 < 2; k8++) {
            const int kb = k8 * 8;
            uint32_t ah[4], al[4];
            ah[0] = SXH[(kb + tig) * 136 + arow];
            ah[1] = SXH[(kb + tig) * 136 + arow + 8];
            ah[2] = SXH[(kb + tig + 4) * 136 + arow];
            ah[3] = SXH[(kb + tig + 4) * 136 + arow + 8];
            if (isQ) {
                al[0] = SXL[(kb + tig) * 136 + arow];
                al[1] = SXL[(kb + tig) * 136 + arow + 8];
                al[2] = SXL[(kb + tig + 4) * 136 + arow];
                al[3] = SXL[(kb + tig + 4) * 136 + arow + 8];
            }
#pragma unroll
            for (int n = 0; n < 10; n++) {
                const uint32_t b0 = SWH[(kb + tig) * 88 + n * 8 + g];
                const uint32_t b1 = SWH[(kb + tig + 4) * 88 + n * 8 + g];
                mma_tf32(c[n], ah, b0, b1);
                if (isQ) mma_tf32(c[n], al, b0, b1);   // xl * Wh compensation
            }
        }

        if (more) store_tile((t + 1) & 1);
        __syncthreads();
    }

    float* o0 = &dst[(size_t)(m0 + warp * 16 + g) * DMODEL];
    float* o1 = o0 + (size_t)8 * DMODEL;
#pragma unroll
    for (int n = 0; n < 10; n++) {
        *(float2*)&o0[n * 8 + 2 * tig] = make_float2(c[n][0], c[n][1]);
        *(float2*)&o1[n * 8 + 2 * tig] = make_float2(c[n][2], c[n][3]);
    }
}

// ---------------- Attention v6: 2 q-rows per lane + ex2 + occ push ----------------
// One block per (b,h). K (pre-scaled by scale*log2e) and V in smem, KPAD=12 (48KB).
// Each lane owns TWO q-rows; broadcast K/V reads (6 LDS feed ~22 FFMA2).
// ex2.approx replaces __expf (log2e folded into K). Unroll 2 (not 4) to shrink
// live-register window; __launch_bounds__(256,4) caps regs at 64 -> 4 blocks/SM.
#define KPAD 12
#define ATTN_SMEM (2 * NY * KPAD * 4)

__global__ void __launch_bounds__(256, 4) attn_kernel(float* __restrict__ qo)
{
    extern __shared__ __align__(16) float fsmem[];
    float* sk = fsmem;               // NY x KPAD (pre-scaled)
    float* sv = fsmem + NY * KPAD;

    const int b = blockIdx.x >> 3;
    const int h = blockIdx.x & 7;
    const float scale = 0.31622776601683794f * 1.4426950408889634f;  // 1/sqrt(10)*log2(e)

    for (int i = threadIdx.x; i < NY * DHEAD; i += 256) {
        const int ky = i / DHEAD, d = i - ky * DHEAD;
        const size_t g = (size_t)(b * NY + ky) * DMODEL + h * DHEAD + d;
        sk[ky * KPAD + d] = g_k[g] * scale;
        sv[ky * KPAD + d] = g_v[g];
    }
    __syncthreads();

    const int warp = threadIdx.x >> 5;
    const int lane = threadIdx.x & 31;

    const int row0 = warp * 64 + lane;
    const int row1 = row0 + 32;
    float* qp0 = &qo[(size_t)(b * NX + row0) * DMODEL + h * DHEAD];
    float* qp1 = &qo[(size_t)(b * NX + row1) * DMODEL + h * DHEAD];

    u64 qv0[5], qv1[5], acc0[5], acc1[5];
#pragma unroll
    for (int c = 0; c < 5; c++) {
        qv0[c] = *(const u64*)&qp0[2 * c];
        qv1[c] = *(const u64*)&qp1[2 * c];
        acc0[c] = 0ULL;
        acc1[c] = 0ULL;
    }
    float ssum0 = 0.0f, ssum1 = 0.0f;

    for (int ky = 0; ky < NY; ky += 2) {
#pragma unroll
        for (int u = 0; u < 2; u++) {
            const float* krow = &sk[(ky + u) * KPAD];   // broadcast (all lanes same addr)
            const float* vrow = &sv[(ky + u) * KPAD];
            const ulonglong2 k01 = *(const ulonglong2*)(krow);
            const ulonglong2 k23 = *(const ulonglong2*)(krow + 4);
            const u64        k4  = *(const u64*)(krow + 8);
            u64 d0 = mul2(qv0[0], k01.x);
            u64 d1 = mul2(qv1[0], k01.x);
            d0 = ffma2(qv0[1], k01.y, d0);  d1 = ffma2(qv1[1], k01.y, d1);
            d0 = ffma2(qv0[2], k23.x, d0);  d1 = ffma2(qv1[2], k23.x, d1);
            d0 = ffma2(qv0[3], k23.y, d0);  d1 = ffma2(qv1[3], k23.y, d1);
            d0 = ffma2(qv0[4], k4,    d0);  d1 = ffma2(qv1[4], k4,    d1);
            float l0, h0, l1, h1;
            unpack2(d0, l0, h0);
            unpack2(d1, l1, h1);
            float e0, e1;
            asm("ex2.approx.f32 %0, %1;" : "=f"(e0) : "f"(l0 + h0));
            asm("ex2.approx.f32 %0, %1;" : "=f"(e1) : "f"(l1 + h1));
            ssum0 += e0;
            ssum1 += e1;
            const u64 e02 = pack2(e0, e0);
            const u64 e12 = pack2(e1, e1);
            const ulonglong2 v01 = *(const ulonglong2*)(vrow);
            const ulonglong2 v23 = *(const ulonglong2*)(vrow + 4);
            const u64        v4  = *(const u64*)(vrow + 8);
            acc0[0] = ffma2(e02, v01.x, acc0[0]);  acc1[0] = ffma2(e12, v01.x, acc1[0]);
            acc0[1] = ffma2(e02, v01.y, acc0[1]);  acc1[1] = ffma2(e12, v01.y, acc1[1]);
            acc0[2] = ffma2(e02, v23.x, acc0[2]);  acc1[2] = ffma2(e12, v23.x, acc1[2]);
            acc0[3] = ffma2(e02, v23.y, acc0[3]);  acc1[3] = ffma2(e12, v23.y, acc1[3]);
            acc0[4] = ffma2(e02, v4,    acc0[4]);  acc1[4] = ffma2(e12, v4,    acc1[4]);
        }
    }

    const float i0 = 1.0f / ssum0;
    const float i1 = 1.0f / ssum1;
    const u64 i02 = pack2(i0, i0);
    const u64 i12 = pack2(i1, i1);
#pragma unroll
    for (int c = 0; c < 5; c++) {
        *(u64*)&qp0[2 * c] = add2(qv0[c], mul2(acc0[c], i02));
        *(u64*)&qp1[2 * c] = add2(qv1[c], mul2(acc1[c], i12));
    }
}

extern "C" void kernel_launch(void* const* d_in, const int* in_sizes, int n_in,
                              void* d_out, int out_size)
{
    const float* x  = (const float*)d_in[0];
    const float* y  = (const float*)d_in[1];
    const float* Wq = (const float*)d_in[2];
    const float* Wk = (const float*)d_in[3];
    const float* Wv = (const float*)d_in[4];
    float* out = (float*)d_out;

    cudaFuncSetAttribute(proj_mma_kernel, cudaFuncAttributeMaxDynamicSharedMemorySize, PJ_SMEM_BYTES);
    cudaFuncSetAttribute(attn_kernel, cudaFuncAttributeMaxDynamicSharedMemorySize, ATTN_SMEM);

    proj_mma_kernel<<<768, 256, PJ_SMEM_BYTES>>>(x, y, Wq, Wk, Wv, out);
    attn_kernel<<<BATCH * NHEAD, 256, ATTN_SMEM>>>(out);  // out = q + att, in place
}

// round 13
// speedup vs baseline: 2.8701x; 1.1697x over previous
#include <cuda_runtime.h>
#include <cstdint>

#define BATCH 64
#define NX    512
#define NY    512
#define NHEAD 8
#define DHEAD 10
#define DMODEL 80     // NHEAD*DHEAD
#define KX    768
#define KY    283
#define KY_PAD 288

typedef unsigned long long u64;

// scratch for K/V projections — device globals per harness rules
__device__ float g_k[BATCH * NY * DMODEL];
__device__ float g_v[BATCH * NY * DMODEL];

// ---------------- tf32 mma helpers (base PTX, works on .target sm_103) ----------------
__device__ __forceinline__ uint32_t f2tf32(float f) {
    uint32_t u; asm("cvt.rna.tf32.f32 %0, %1;" : "=r"(u) : "f"(f)); return u;
}
__device__ __forceinline__ void mma_tf32(float c[4], const uint32_t a[4],
                                         uint32_t b0, uint32_t b1) {
    asm volatile(
        "mma.sync.aligned.m16n8k8.row.col.f32.tf32.tf32.f32 "
        "{%0,%1,%2,%3}, {%4,%5,%6,%7}, {%8,%9}, {%0,%1,%2,%3};"
        : "+f"(c[0]), "+f"(c[1]), "+f"(c[2]), "+f"(c[3])
        : "r"(a[0]), "r"(a[1]), "r"(a[2]), "r"(a[3]), "r"(b0), "r"(b1));
}

// ---------------- Projection via mma.sync tf32 (2-term compensated Q) ----------------
// 768 CTAs x 256 thr (8 warps): [0,256) Q = (xh+xl)@tf32(Wq) ; [256,512) K ; [512,768) V.
// Block tile 128 rows x 80 cols; warp tile m16 x n80; K chunk = 16 (2 k8 steps).
#define SXH_OFF 0
#define SXL_OFF 4352            // 2*16*136
#define SWH_OFF 8704
#define PJ_SMEM_U32 11520       // + 2*16*88
#define PJ_SMEM_BYTES (PJ_SMEM_U32 * 4)

__global__ void __launch_bounds__(256) proj_mma_kernel(
    const float* __restrict__ x, const float* __restrict__ y,
    const float* __restrict__ Wq, const float* __restrict__ Wk,
    const float* __restrict__ Wv, float* __restrict__ out)
{
    extern __shared__ __align__(16) uint32_t su[];
    uint32_t* sxh = su + SXH_OFF;
    uint32_t* sxl = su + SXL_OFF;
    uint32_t* swh = su + SWH_OFF;

    const int tid   = threadIdx.x;
    const int warp  = tid >> 5;
    const int lane  = tid & 31;
    const int g     = lane >> 2;       // 0..7
    const int tig   = lane & 3;        // 0..3
    const int which = blockIdx.x >> 8; // 0=Q, 1=K, 2=V
    const bool isQ  = (which == 0);
    const int m0    = (blockIdx.x & 255) * 128;

    const float* W = isQ ? Wq : ((which == 1) ? Wk : Wv);
    float* dst     = isQ ? out : ((which == 1) ? g_k : g_v);
    const int Kdim = isQ ? KX : KY;
    const int ntile = (isQ ? KX : KY_PAD) >> 4;   // 48 or 18

    float4 pfx[2];
    float  pfy[8];
    float  pfw[5];

    auto load_tile = [&](int t) {
        const int k0 = t << 4;
        if (isQ) {
#pragma unroll
            for (int s = 0; s < 2; s++) {
                const int i = tid + s * 256;
                const int r = i >> 2, q4 = i & 3;
                pfx[s] = *(const float4*)&x[(size_t)(m0 + r) * KX + k0 + q4 * 4];
            }
        } else {
#pragma unroll
            for (int s = 0; s < 8; s++) {
                const int i = tid + s * 256;
                const int r = i >> 4, kk = i & 15;
                const int k = k0 + kk;
                pfy[s] = (k < Kdim) ? y[(size_t)(m0 + r) * KY + k] : 0.0f;
            }
        }
#pragma unroll
        for (int s = 0; s < 5; s++) {
            const int i = tid + s * 256;
            const int kk = i / 80, j = i - kk * 80;
            const int k = k0 + kk;
            pfw[s] = (k < Kdim) ? W[(size_t)k * 80 + j] : 0.0f;
        }
    };
    auto store_tile = [&](int buf) {
        if (isQ) {
#pragma unroll
            for (int s = 0; s < 2; s++) {
                const int i = tid + s * 256;
                const int r = i >> 2, q4 = i & 3;
                const float v[4] = { pfx[s].x, pfx[s].y, pfx[s].z, pfx[s].w };
#pragma unroll
                for (int j = 0; j < 4; j++) {
                    const uint32_t hbits = f2tf32(v[j]);
                    const float lo = v[j] - __uint_as_float(hbits);
                    const int a = buf * 2176 + (q4 * 4 + j) * 136 + r;
                    sxh[a] = hbits;
                    sxl[a] = f2tf32(lo);
                }
            }
        } else {
#pragma unroll
            for (int s = 0; s < 8; s++) {
                const int i = tid + s * 256;
                const int r = i >> 4, kk = i & 15;
                sxh[buf * 2176 + kk * 136 + r] = f2tf32(pfy[s]);
            }
        }
#pragma unroll
        for (int s = 0; s < 5; s++) {
            const int i = tid + s * 256;
            const int kk = i / 80, j = i - kk * 80;
            swh[buf * 1408 + kk * 88 + j] = f2tf32(pfw[s]);
        }
    };

    float c[10][4];
#pragma unroll
    for (int n = 0; n < 10; n++)
#pragma unroll
        for (int j = 0; j < 4; j++) c[n][j] = 0.0f;

    load_tile(0);
    store_tile(0);
    __syncthreads();

    const int arow = warp * 16 + g;

    for (int t = 0; t < ntile; t++) {
        const int cur = t & 1;
        const bool more = (t + 1 < ntile);
        if (more) load_tile(t + 1);

        const uint32_t* SXH = sxh + cur * 2176;
        const uint32_t* SXL = sxl + cur * 2176;
        const uint32_t* SWH = swh + cur * 1408;

#pragma unroll
        for (int k8 = 0; k8 < 2; k8++) {
            const int kb = k8 * 8;
            uint32_t ah[4], al[4];
            ah[0] = SXH[(kb + tig) * 136 + arow];
            ah[1] = SXH[(kb + tig) * 136 + arow + 8];
            ah[2] = SXH[(kb + tig + 4) * 136 + arow];
            ah[3] = SXH[(kb + tig + 4) * 136 + arow + 8];
            if (isQ) {
                al[0] = SXL[(kb + tig) * 136 + arow];
                al[1] = SXL[(kb + tig) * 136 + arow + 8];
                al[2] = SXL[(kb + tig + 4) * 136 + arow];
                al[3] = SXL[(kb + tig + 4) * 136 + arow + 8];
            }
#pragma unroll
            for (int n = 0; n < 10; n++) {
                const uint32_t b0 = SWH[(kb + tig) * 88 + n * 8 + g];
                const uint32_t b1 = SWH[(kb + tig + 4) * 88 + n * 8 + g];
                mma_tf32(c[n], ah, b0, b1);
                if (isQ) mma_tf32(c[n], al, b0, b1);   // xl * Wh compensation
            }
        }

        if (more) store_tile((t + 1) & 1);
        __syncthreads();
    }

    float* o0 = &dst[(size_t)(m0 + warp * 16 + g) * DMODEL];
    float* o1 = o0 + (size_t)8 * DMODEL;
#pragma unroll
    for (int n = 0; n < 10; n++) {
        *(float2*)&o0[n * 8 + 2 * tig] = make_float2(c[n][0], c[n][1]);
        *(float2*)&o1[n * 8 + 2 * tig] = make_float2(c[n][2], c[n][3]);
    }
}

// ---------------- Attention v7: tensor-core flash-attention ----------------
// One block per (b,h), 8 warps. K stored transposed [k(16)][key] (stride 520,
// rows 10..15 zero, pre-scaled by scale*log2e, tf32); V stored [key][n] (stride
// 24, cols 10..15 zero, tf32). Warp owns m16 q-rows per pass (4 passes).
// Per 16-key chunk: 4 score MMAs -> ex2 on C-frags -> quad-shuffle P into
// A-frag layout -> 4 AV MMAs. Row sums in regs (quad-reduced at end).
// out = q + (P@V)/rowsum, in place on d_out.
#define SKSTR 520
#define SVSTR 24
#define ATTN_SMEM ((16 * SKSTR + 512 * SVSTR) * 4)   // 82432 B -> 2 blocks/SM

__global__ void __launch_bounds__(256, 2) attn_kernel(float* __restrict__ qo)
{
    extern __shared__ __align__(16) float fs[];
    float* sk = fs;                  // [16][SKSTR]
    float* sv = fs + 16 * SKSTR;     // [512][SVSTR]

    const int b = blockIdx.x >> 3;
    const int h = blockIdx.x & 7;
    const int tid = threadIdx.x;
    const float scale = 0.31622776601683794f * 1.4426950408889634f;  // 1/sqrt(10)*log2e

    // stage K transposed + scaled + tf32
    for (int i = tid; i < NY * DHEAD; i += 256) {
        const int key = i / DHEAD, d = i - key * DHEAD;
        const float v = g_k[(size_t)(b * NY + key) * DMODEL + h * DHEAD + d] * scale;
        sk[d * SKSTR + key] = __uint_as_float(f2tf32(v));
    }
    // zero K pad rows 10..15 (keys 0..511)
    for (int i = tid; i < 6 * 512; i += 256) {
        const int r = 10 + (i >> 9), key = i & 511;
        sk[r * SKSTR + key] = 0.0f;
    }
    // stage V tf32
    for (int i = tid; i < NY * DHEAD; i += 256) {
        const int key = i / DHEAD, d = i - key * DHEAD;
        sv[key * SVSTR + d] =
            __uint_as_float(f2tf32(g_v[(size_t)(b * NY + key) * DMODEL + h * DHEAD + d]));
    }
    // zero V pad cols 10..15 (all keys)
    for (int i = tid; i < 6 * 512; i += 256) {
        const int n = 10 + (i >> 9), key = i & 511;
        sv[key * SVSTR + n] = 0.0f;
    }
    __syncthreads();

    const int warp = tid >> 5;
    const int lane = tid & 31;
    const int g    = lane >> 2;      // 0..7
    const int tig  = lane & 3;       // 0..3
    const int srcA = (lane & ~3) | (tig >> 1);
    const int srcB = srcA + 2;
    const bool odd = (tig & 1);

    const float* pK0 = sk + tig * SKSTR + g;        // k rows tig / tig+4
    const float* pK1 = sk + (tig + 4) * SKSTR + g;
    const float* pV  = sv + tig * SVSTR + g;        // key rows tig / tig+4 (+8s offsets)

#pragma unroll 1
    for (int pass = 0; pass < 4; pass++) {
        const int qrow0 = (pass * 8 + warp) * 16;
        float* qb = qo + (size_t)(b * NX + qrow0) * DMODEL + h * DHEAD;

        // Q A-frags (tf32), k padded to 16 with zeros
        uint32_t qa[2][4];
#pragma unroll
        for (int s = 0; s < 2; s++) {
            const int ka = 8 * s + tig, kc = 8 * s + tig + 4;
            qa[s][0] = (ka < DHEAD) ? f2tf32(qb[g * DMODEL + ka]) : 0u;
            qa[s][1] = (ka < DHEAD) ? f2tf32(qb[(g + 8) * DMODEL + ka]) : 0u;
            qa[s][2] = (kc < DHEAD) ? f2tf32(qb[g * DMODEL + kc]) : 0u;
            qa[s][3] = (kc < DHEAD) ? f2tf32(qb[(g + 8) * DMODEL + kc]) : 0u;
        }

        float av0[4] = {0.f, 0.f, 0.f, 0.f};   // out cols 0..7
        float av1[4] = {0.f, 0.f, 0.f, 0.f};   // out cols 8..15 (8,9 real)
        float rs0 = 0.f, rs1 = 0.f;            // row sums (rows g, g+8)

        for (int ch = 0; ch < 32; ch++) {
            const int key0 = ch * 16;
            float e[8];
            // --- scores: two n8 key tiles ---
#pragma unroll
            for (int t = 0; t < 2; t++) {
                float c[4] = {0.f, 0.f, 0.f, 0.f};
                const int kt = key0 + t * 8;
                {
                    const uint32_t b0 = __float_as_uint(pK0[kt]);
                    const uint32_t b1 = __float_as_uint(pK1[kt]);
                    mma_tf32(c, qa[0], b0, b1);
                }
                {
                    const uint32_t b0 = __float_as_uint(pK0[8 * SKSTR + kt]);
                    const uint32_t b1 = __float_as_uint(pK1[8 * SKSTR + kt]);
                    mma_tf32(c, qa[1], b0, b1);
                }
#pragma unroll
                for (int j = 0; j < 4; j++)
                    asm("ex2.approx.f32 %0, %1;" : "=f"(e[t * 4 + j]) : "f"(c[j]));
                rs0 += e[t * 4 + 0] + e[t * 4 + 1];
                rs1 += e[t * 4 + 2] + e[t * 4 + 3];
            }
            // --- AV: two k8 steps; P C-frags -> A-frags via quad shuffles ---
#pragma unroll
            for (int s = 0; s < 2; s++) {
                const float x0 = __shfl_sync(0xffffffffu, e[s * 4 + 0], srcA);
                const float x1 = __shfl_sync(0xffffffffu, e[s * 4 + 1], srcA);
                const float x2 = __shfl_sync(0xffffffffu, e[s * 4 + 2], srcA);
                const float x3 = __shfl_sync(0xffffffffu, e[s * 4 + 3], srcA);
                const float y0 = __shfl_sync(0xffffffffu, e[s * 4 + 0], srcB);
                const float y1 = __shfl_sync(0xffffffffu, e[s * 4 + 1], srcB);
                const float y2 = __shfl_sync(0xffffffffu, e[s * 4 + 2], srcB);
                const float y3 = __shfl_sync(0xffffffffu, e[s * 4 + 3], srcB);
                uint32_t pa[4];
                pa[0] = __float_as_uint(odd ? x1 : x0);   // P(g,      8s+tig)
                pa[1] = __float_as_uint(odd ? x3 : x2);   // P(g+8,    8s+tig)
                pa[2] = __float_as_uint(odd ? y1 : y0);   // P(g,      8s+tig+4)
                pa[3] = __float_as_uint(odd ? y3 : y2);   // P(g+8,    8s+tig+4)
                const int kb = key0 + 8 * s;
                {
                    const uint32_t b0 = __float_as_uint(pV[kb * SVSTR]);
                    const uint32_t b1 = __float_as_uint(pV[(kb + 4) * SVSTR]);
                    mma_tf32(av0, pa, b0, b1);
                }
                {
                    const uint32_t b0 = __float_as_uint(pV[kb * SVSTR + 8]);
                    const uint32_t b1 = __float_as_uint(pV[(kb + 4) * SVSTR + 8]);
                    mma_tf32(av1, pa, b0, b1);
                }
            }
        }

        // reduce row sums across the quad (cols split over tig)
        rs0 += __shfl_xor_sync(0xffffffffu, rs0, 1);
        rs0 += __shfl_xor_sync(0xffffffffu, rs0, 2);
        rs1 += __shfl_xor_sync(0xffffffffu, rs1, 1);
        rs1 += __shfl_xor_sync(0xffffffffu, rs1, 2);
        const float inv0 = 1.0f / rs0;
        const float inv1 = 1.0f / rs1;

        // out = q + av/rowsum  (rows g, g+8; cols 2tig,2tig+1; tig==0 also 8,9)
        float* o0 = qb + g * DMODEL;
        float* o1 = qb + (g + 8) * DMODEL;
        {
            float2 q0 = *(float2*)&o0[2 * tig];
            float2 q1 = *(float2*)&o1[2 * tig];
            *(float2*)&o0[2 * tig] = make_float2(q0.x + av0[0] * inv0, q0.y + av0[1] * inv0);
            *(float2*)&o1[2 * tig] = make_float2(q1.x + av0[2] * inv1, q1.y + av0[3] * inv1);
        }
        if (tig == 0) {
            float2 q0 = *(float2*)&o0[8];
            float2 q1 = *(float2*)&o1[8];
            *(float2*)&o0[8] = make_float2(q0.x + av1[0] * inv0, q0.y + av1[1] * inv0);
            *(float2*)&o1[8] = make_float2(q1.x + av1[2] * inv1, q1.y + av1[3] * inv1);
        }
    }
}

extern "C" void kernel_launch(void* const* d_in, const int* in_sizes, int n_in,
                              void* d_out, int out_size)
{
    const float* x  = (const float*)d_in[0];
    const float* y  = (const float*)d_in[1];
    const float* Wq = (const float*)d_in[2];
    const float* Wk = (const float*)d_in[3];
    const float* Wv = (const float*)d_in[4];
    float* out = (float*)d_out;

    cudaFuncSetAttribute(proj_mma_kernel, cudaFuncAttributeMaxDynamicSharedMemorySize, PJ_SMEM_BYTES);
    cudaFuncSetAttribute(attn_kernel, cudaFuncAttributeMaxDynamicSharedMemorySize, ATTN_SMEM);

    proj_mma_kernel<<<768, 256, PJ_SMEM_BYTES>>>(x, y, Wq, Wk, Wv, out);
    attn_kernel<<<BATCH * NHEAD, 256, ATTN_SMEM>>>(out);  // out = q + att, in place
}

// round 15
// speedup vs baseline: 3.6019x; 1.2549x over previous
#include <cuda_runtime.h>
#include <cuda_fp16.h>
#include <cstdint>

#define BATCH 64
#define NX    512
#define NY    512
#define NHEAD 8
#define DHEAD 10
#define DMODEL 80     // NHEAD*DHEAD
#define KX    768
#define KY    283
#define KY_PAD 288

// scratch for K/V projections — device globals per harness rules
__device__ float g_k[BATCH * NY * DMODEL];
__device__ float g_v[BATCH * NY * DMODEL];

// ---------------- tf32 / f16 mma helpers (base PTX, works on .target sm_103) ----------------
__device__ __forceinline__ uint32_t f2tf32(float f) {
    uint32_t u; asm("cvt.rna.tf32.f32 %0, %1;" : "=r"(u) : "f"(f)); return u;
}
__device__ __forceinline__ void mma_tf32(float c[4], const uint32_t a[4],
                                         uint32_t b0, uint32_t b1) {
    asm volatile(
        "mma.sync.aligned.m16n8k8.row.col.f32.tf32.tf32.f32 "
        "{%0,%1,%2,%3}, {%4,%5,%6,%7}, {%8,%9}, {%0,%1,%2,%3};"
        : "+f"(c[0]), "+f"(c[1]), "+f"(c[2]), "+f"(c[3])
        : "r"(a[0]), "r"(a[1]), "r"(a[2]), "r"(a[3]), "r"(b0), "r"(b1));
}
__device__ __forceinline__ void mma_f16(float c[4], const uint32_t a[4],
                                        uint32_t b0, uint32_t b1) {
    asm volatile(
        "mma.sync.aligned.m16n8k16.row.col.f32.f16.f16.f32 "
        "{%0,%1,%2,%3}, {%4,%5,%6,%7}, {%8,%9}, {%0,%1,%2,%3};"
        : "+f"(c[0]), "+f"(c[1]), "+f"(c[2]), "+f"(c[3])
        : "r"(a[0]), "r"(a[1]), "r"(a[2]), "r"(a[3]), "r"(b0), "r"(b1));
}
__device__ __forceinline__ uint32_t f16x2(float lo, float hi) {
    uint32_t u;  // cvt d, a(hi), b(lo): lo -> lower half
    asm("cvt.rn.f16x2.f32 %0, %1, %2;" : "=r"(u) : "f"(hi), "f"(lo));
    return u;
}
__device__ __forceinline__ uint16_t f2h(float f) {
    uint16_t h; asm("cvt.rn.f16.f32 %0, %1;" : "=h"(h) : "f"(f)); return h;
}

// ---------------- Projection via mma.sync tf32 (2-term compensated Q) ----------------
// (unchanged from R12/R13 — 110us, verified)
#define SXH_OFF 0
#define SXL_OFF 4352            // 2*16*136
#define SWH_OFF 8704
#define PJ_SMEM_U32 11520       // + 2*16*88
#define PJ_SMEM_BYTES (PJ_SMEM_U32 * 4)

__global__ void __launch_bounds__(256) proj_mma_kernel(
    const float* __restrict__ x, const float* __restrict__ y,
    const float* __restrict__ Wq, const float* __restrict__ Wk,
    const float* __restrict__ Wv, float* __restrict__ out)
{
    extern __shared__ __align__(16) uint32_t su[];
    uint32_t* sxh = su + SXH_OFF;
    uint32_t* sxl = su + SXL_OFF;
    uint32_t* swh = su + SWH_OFF;

    const int tid   = threadIdx.x;
    const int warp  = tid >> 5;
    const int lane  = tid & 31;
    const int g     = lane >> 2;       // 0..7
    const int tig   = lane & 3;        // 0..3
    const int which = blockIdx.x >> 8; // 0=Q, 1=K, 2=V
    const bool isQ  = (which == 0);
    const int m0    = (blockIdx.x & 255) * 128;

    const float* W = isQ ? Wq : ((which == 1) ? Wk : Wv);
    float* dst     = isQ ? out : ((which == 1) ? g_k : g_v);
    const int Kdim = isQ ? KX : KY;
    const int ntile = (isQ ? KX : KY_PAD) >> 4;   // 48 or 18

    float4 pfx[2];
    float  pfy[8];
    float  pfw[5];

    auto load_tile = [&](int t) {
        const int k0 = t << 4;
        if (isQ) {
#pragma unroll
            for (int s = 0; s < 2; s++) {
                const int i = tid + s * 256;
                const int r = i >> 2, q4 = i & 3;
                pfx[s] = *(const float4*)&x[(size_t)(m0 + r) * KX + k0 + q4 * 4];
            }
        } else {
#pragma unroll
            for (int s = 0; s < 8; s++) {
                const int i = tid + s * 256;
                const int r = i >> 4, kk = i & 15;
                const int k = k0 + kk;
                pfy[s] = (k < Kdim) ? y[(size_t)(m0 + r) * KY + k] : 0.0f;
            }
        }
#pragma unroll
        for (int s = 0; s < 5; s++) {
            const int i = tid + s * 256;
            const int kk = i / 80, j = i - kk * 80;
            const int k = k0 + kk;
            pfw[s] = (k < Kdim) ? W[(size_t)k * 80 + j] : 0.0f;
        }
    };
    auto store_tile = [&](int buf) {
        if (isQ) {
#pragma unroll
            for (int s = 0; s < 2; s++) {
                const int i = tid + s * 256;
                const int r = i >> 2, q4 = i & 3;
                const float v[4] = { pfx[s].x, pfx[s].y, pfx[s].z, pfx[s].w };
#pragma unroll
                for (int j = 0; j < 4; j++) {
                    const uint32_t hbits = f2tf32(v[j]);
                    const float lo = v[j] - __uint_as_float(hbits);
                    const int a = buf * 2176 + (q4 * 4 + j) * 136 + r;
                    sxh[a] = hbits;
                    sxl[a] = f2tf32(lo);
                }
            }
        } else {
#pragma unroll
            for (int s = 0; s < 8; s++) {
                const int i = tid + s * 256;
                const int r = i >> 4, kk = i & 15;
                sxh[buf * 2176 + kk * 136 + r] = f2tf32(pfy[s]);
            }
        }
#pragma unroll
        for (int s = 0; s < 5; s++) {
            const int i = tid + s * 256;
            const int kk = i / 80, j = i - kk * 80;
            swh[buf * 1408 + kk * 88 + j] = f2tf32(pfw[s]);
        }
    };

    float c[10][4];
#pragma unroll
    for (int n = 0; n < 10; n++)
#pragma unroll
        for (int j = 0; j < 4; j++) c[n][j] = 0.0f;

    load_tile(0);
    store_tile(0);
    __syncthreads();

    const int arow = warp * 16 + g;

    for (int t = 0; t < ntile; t++) {
        const int cur = t & 1;
        const bool more = (t + 1 < ntile);
        if (more) load_tile(t + 1);

        const uint32_t* SXH = sxh + cur * 2176;
        const uint32_t* SXL = sxl + cur * 2176;
        const uint32_t* SWH = swh + cur * 1408;

#pragma unroll
        for (int k8 = 0; k8 < 2; k8++) {
            const int kb = k8 * 8;
            uint32_t ah[4], al[4];
            ah[0] = SXH[(kb + tig) * 136 + arow];
            ah[1] = SXH[(kb + tig) * 136 + arow + 8];
            ah[2] = SXH[(kb + tig + 4) * 136 + arow];
            ah[3] = SXH[(kb + tig + 4) * 136 + arow + 8];
            if (isQ) {
                al[0] = SXL[(kb + tig) * 136 + arow];
                al[1] = SXL[(kb + tig) * 136 + arow + 8];
                al[2] = SXL[(kb + tig + 4) * 136 + arow];
                al[3] = SXL[(kb + tig + 4) * 136 + arow + 8];
            }
#pragma unroll
            for (int n = 0; n < 10; n++) {
                const uint32_t b0 = SWH[(kb + tig) * 88 + n * 8 + g];
                const uint32_t b1 = SWH[(kb + tig + 4) * 88 + n * 8 + g];
                mma_tf32(c[n], ah, b0, b1);
                if (isQ) mma_tf32(c[n], al, b0, b1);   // xl * Wh compensation
            }
        }

        if (more) store_tile((t + 1) & 1);
        __syncthreads();
    }

    float* o0 = &dst[(size_t)(m0 + warp * 16 + g) * DMODEL];
    float* o1 = o0 + (size_t)8 * DMODEL;
#pragma unroll
    for (int n = 0; n < 10; n++) {
        *(float2*)&o0[n * 8 + 2 * tig] = make_float2(c[n][0], c[n][1]);
        *(float2*)&o1[n * 8 + 2 * tig] = make_float2(c[n][2], c[n][3]);
    }
}

// ---------------- Attention v8: tensor FA, shuffle-free (f16 P/V for AV) ----------------
// One block per (b,h), 8 warps. K transposed [k(16)][key] f32-tf32 (stride 520,
// rows 10..15 zero, pre-scaled by scale*log2e). V transposed [n(16)][key] in
// f16 (uint16_t storage; stride 536 halves; word-bank g*12+tig mod 32 distinct).
// Per 16-key chunk: 4 tf32 score MMAs -> ex2 on C-frags -> cvt.rn.f16x2 packs
// C-frags DIRECTLY into f16 m16n8k16 A-frag layout (identical element map — no
// shuffles) -> 2 f16 AV MMAs. Row sums quad-reduced at end.
// smem 50.4KB + 64-reg cap -> 4 blocks/SM, grid 512 = 1 wave.
#define SKSTR 520
#define SVSTR 536                                  // halves per n-row
#define SV_OFF (16 * SKSTR)                        // f32 index where V (half) starts
#define ATTN_SMEM (16 * SKSTR * 4 + 16 * SVSTR * 2)  // 33280 + 17152 = 50432

__global__ void __launch_bounds__(256, 4) attn_kernel(float* __restrict__ qo)
{
    extern __shared__ __align__(16) float fs[];
    float* sk = fs;                                // [16][SKSTR] f32
    uint16_t* svh = (uint16_t*)(fs + SV_OFF);      // [16][SVSTR] f16 bits

    const int b = blockIdx.x >> 3;
    const int h = blockIdx.x & 7;
    const int tid = threadIdx.x;
    const float scale = 0.31622776601683794f * 1.4426950408889634f;  // 1/sqrt(10)*log2e

    // stage K transposed + scaled + tf32
    for (int i = tid; i < NY * DHEAD; i += 256) {
        const int key = i / DHEAD, d = i - key * DHEAD;
        const float v = g_k[(size_t)(b * NY + key) * DMODEL + h * DHEAD + d] * scale;
        sk[d * SKSTR + key] = __uint_as_float(f2tf32(v));
    }
    for (int i = tid; i < 6 * 512; i += 256) {     // zero K pad rows 10..15
        const int r = 10 + (i >> 9), key = i & 511;
        sk[r * SKSTR + key] = 0.0f;
    }
    // stage V transposed f16: svh[n][key]
    for (int i = tid; i < 512 * 16; i += 256) {
        const int key = i >> 4, n = i & 15;
        const float v = (n < DHEAD)
            ? g_v[(size_t)(b * NY + key) * DMODEL + h * DHEAD + n] : 0.0f;
        svh[n * SVSTR + key] = f2h(v);
    }
    __syncthreads();

    const int warp = tid >> 5;
    const int lane = tid & 31;
    const int g    = lane >> 2;      // 0..7
    const int tig  = lane & 3;       // 0..3

    const float* pK0 = sk + tig * SKSTR + g;        // k rows tig / tig+4
    const float* pK1 = sk + (tig + 4) * SKSTR + g;
    const uint16_t* pV = svh + 2 * tig;             // + n*SVSTR + key offsets

#pragma unroll 1
    for (int pass = 0; pass < 4; pass++) {
        const int qrow0 = (pass * 8 + warp) * 16;
        float* qb = qo + (size_t)(b * NX + qrow0) * DMODEL + h * DHEAD;

        // Q A-frags (tf32), k padded to 16 with zeros
        uint32_t qa[2][4];
#pragma unroll
        for (int s = 0; s < 2; s++) {
            const int ka = 8 * s + tig, kc = 8 * s + tig + 4;
            qa[s][0] = (ka < DHEAD) ? f2tf32(qb[g * DMODEL + ka]) : 0u;
            qa[s][1] = (ka < DHEAD) ? f2tf32(qb[(g + 8) * DMODEL + ka]) : 0u;
            qa[s][2] = (kc < DHEAD) ? f2tf32(qb[g * DMODEL + kc]) : 0u;
            qa[s][3] = (kc < DHEAD) ? f2tf32(qb[(g + 8) * DMODEL + kc]) : 0u;
        }

        float av0[4] = {0.f, 0.f, 0.f, 0.f};   // out cols 0..7
        float av1[4] = {0.f, 0.f, 0.f, 0.f};   // out cols 8..15 (8,9 real)
        float rs0 = 0.f, rs1 = 0.f;            // row sums (rows g, g+8)

        for (int ch = 0; ch < 32; ch++) {
            const int key0 = ch * 16;
            float e0[4], e1[4];
            // --- scores: two n8 key tiles -> ex2 ---
#pragma unroll
            for (int t = 0; t < 2; t++) {
                float c[4] = {0.f, 0.f, 0.f, 0.f};
                const int kt = key0 + t * 8;
                mma_tf32(c, qa[0], __float_as_uint(pK0[kt]),
                                   __float_as_uint(pK1[kt]));
                mma_tf32(c, qa[1], __float_as_uint(pK0[8 * SKSTR + kt]),
                                   __float_as_uint(pK1[8 * SKSTR + kt]));
                float* e = t ? e1 : e0;
#pragma unroll
                for (int j = 0; j < 4; j++)
                    asm("ex2.approx.f32 %0, %1;" : "=f"(e[j]) : "f"(c[j]));
                rs0 += e[0] + e[1];
                rs1 += e[2] + e[3];
            }
            // --- P C-frags == f16 A-frags (no shuffle) ---
            uint32_t pa[4];
            pa[0] = f16x2(e0[0], e0[1]);   // A(g,   2tig), A(g,   2tig+1)
            pa[1] = f16x2(e0[2], e0[3]);   // A(g+8, 2tig), A(g+8, 2tig+1)
            pa[2] = f16x2(e1[0], e1[1]);   // A(g,   2tig+8), ...
            pa[3] = f16x2(e1[2], e1[3]);   // A(g+8, 2tig+8), ...
            // --- AV: 2 f16 m16n8k16 MMAs; B-frags from svh[n][key] ---
            {
                const uint16_t* p = pV + g * SVSTR + key0;
                const uint32_t b0 = *(const uint32_t*)(p);      // keys 2tig,2tig+1
                const uint32_t b1 = *(const uint32_t*)(p + 8);  // keys 2tig+8,+9
                mma_f16(av0, pa, b0, b1);
            }
            {
                const uint16_t* p = pV + (8 + g) * SVSTR + key0;
                const uint32_t b0 = *(const uint32_t*)(p);
                const uint32_t b1 = *(const uint32_t*)(p + 8);
                mma_f16(av1, pa, b0, b1);
            }
        }

        // reduce row sums across the quad (cols split over tig)
        rs0 += __shfl_xor_sync(0xffffffffu, rs0, 1);
        rs0 += __shfl_xor_sync(0xffffffffu, rs0, 2);
        rs1 += __shfl_xor_sync(0xffffffffu, rs1, 1);
        rs1 += __shfl_xor_sync(0xffffffffu, rs1, 2);
        const float inv0 = 1.0f / rs0;
        const float inv1 = 1.0f / rs1;

        // out = q + av/rowsum  (rows g, g+8; cols 2tig,2tig+1; tig==0 also 8,9)
        float* o0 = qb + g * DMODEL;
        float* o1 = qb + (g + 8) * DMODEL;
        {
            float2 q0 = *(float2*)&o0[2 * tig];
            float2 q1 = *(float2*)&o1[2 * tig];
            *(float2*)&o0[2 * tig] = make_float2(q0.x + av0[0] * inv0, q0.y + av0[1] * inv0);
            *(float2*)&o1[2 * tig] = make_float2(q1.x + av0[2] * inv1, q1.y + av0[3] * inv1);
        }
        if (tig == 0) {
            float2 q0 = *(float2*)&o0[8];
            float2 q1 = *(float2*)&o1[8];
            *(float2*)&o0[8] = make_float2(q0.x + av1[0] * inv0, q0.y + av1[1] * inv0);
            *(float2*)&o1[8] = make_float2(q1.x + av1[2] * inv1, q1.y + av1[3] * inv1);
        }
    }
}

extern "C" void kernel_launch(void* const* d_in, const int* in_sizes, int n_in,
                              void* d_out, int out_size)
{
    const float* x  = (const float*)d_in[0];
    const float* y  = (const float*)d_in[1];
    const float* Wq = (const float*)d_in[2];
    const float* Wk = (const float*)d_in[3];
    const float* Wv = (const float*)d_in[4];
    float* out = (float*)d_out;

    cudaFuncSetAttribute(proj_mma_kernel, cudaFuncAttributeMaxDynamicSharedMemorySize, PJ_SMEM_BYTES);
    cudaFuncSetAttribute(attn_kernel, cudaFuncAttributeMaxDynamicSharedMemorySize, ATTN_SMEM);

    proj_mma_kernel<<<768, 256, PJ_SMEM_BYTES>>>(x, y, Wq, Wk, Wv, out);
    attn_kernel<<<BATCH * NHEAD, 256, ATTN_SMEM>>>(out);  // out = q + att, in place
}

// round 16
// speedup vs baseline: 4.1140x; 1.1422x over previous
#include <cuda_runtime.h>
#include <cuda_fp16.h>
#include <cstdint>

#define BATCH 64
#define NX    512
#define NY    512
#define NHEAD 8
#define DHEAD 10
#define DMODEL 80     // NHEAD*DHEAD
#define KX    768
#define KY    283
#define KY_PAD 288

// scratch for K/V projections — device globals per harness rules
__device__ float g_k[BATCH * NY * DMODEL];
__device__ float g_v[BATCH * NY * DMODEL];

// ---------------- tf32 / f16 mma helpers (base PTX, works on .target sm_103) ----------------
__device__ __forceinline__ uint32_t f2tf32(float f) {
    uint32_t u; asm("cvt.rna.tf32.f32 %0, %1;" : "=r"(u) : "f"(f)); return u;
}
__device__ __forceinline__ void mma_tf32(float c[4], const uint32_t a[4],
                                         uint32_t b0, uint32_t b1) {
    asm volatile(
        "mma.sync.aligned.m16n8k8.row.col.f32.tf32.tf32.f32 "
        "{%0,%1,%2,%3}, {%4,%5,%6,%7}, {%8,%9}, {%0,%1,%2,%3};"
        : "+f"(c[0]), "+f"(c[1]), "+f"(c[2]), "+f"(c[3])
        : "r"(a[0]), "r"(a[1]), "r"(a[2]), "r"(a[3]), "r"(b0), "r"(b1));
}
__device__ __forceinline__ void mma_f16(float c[4], const uint32_t a[4],
                                        uint32_t b0, uint32_t b1) {
    asm volatile(
        "mma.sync.aligned.m16n8k16.row.col.f32.f16.f16.f32 "
        "{%0,%1,%2,%3}, {%4,%5,%6,%7}, {%8,%9}, {%0,%1,%2,%3};"
        : "+f"(c[0]), "+f"(c[1]), "+f"(c[2]), "+f"(c[3])
        : "r"(a[0]), "r"(a[1]), "r"(a[2]), "r"(a[3]), "r"(b0), "r"(b1));
}
__device__ __forceinline__ uint32_t f16x2(float lo, float hi) {
    uint32_t u;  // cvt d, a(hi), b(lo): lo -> lower half
    asm("cvt.rn.f16x2.f32 %0, %1, %2;" : "=r"(u) : "f"(hi), "f"(lo));
    return u;
}
__device__ __forceinline__ uint16_t f2h(float f) {
    uint16_t h; asm("cvt.rn.f16.f32 %0, %1;" : "=h"(h) : "f"(f)); return h;
}

// ---------------- Projection via mma.sync tf32 (single-term, uniform Q/K/V) ----------------
// 768 CTAs x 256 thr (8 warps): [0,256) Q ; [256,512) K ; [512,768) V.
// Block tile 128 rows x 80 cols; warp tile m16 x n80; K chunk = 16 (2 k8 steps).
// Single-term tf32 everywhere: error budget measured ~2e-4 per dropped term,
// combined ~3e-4 << 1e-3. Smem: A [2][16][136] + B [2][16][88] = 28KB.
#define SXH_OFF 0
#define SWH_OFF 4352            // 2*16*136
#define PJ_SMEM_U32 7168        // + 2*16*88
#define PJ_SMEM_BYTES (PJ_SMEM_U32 * 4)

__global__ void __launch_bounds__(256) proj_mma_kernel(
    const float* __restrict__ x, const float* __restrict__ y,
    const float* __restrict__ Wq, const float* __restrict__ Wk,
    const float* __restrict__ Wv, float* __restrict__ out)
{
    extern __shared__ __align__(16) uint32_t su[];
    uint32_t* sxh = su + SXH_OFF;
    uint32_t* swh = su + SWH_OFF;

    const int tid   = threadIdx.x;
    const int warp  = tid >> 5;
    const int lane  = tid & 31;
    const int g     = lane >> 2;       // 0..7
    const int tig   = lane & 3;        // 0..3
    const int which = blockIdx.x >> 8; // 0=Q, 1=K, 2=V
    const bool isQ  = (which == 0);
    const int m0    = (blockIdx.x & 255) * 128;

    const float* W = isQ ? Wq : ((which == 1) ? Wk : Wv);
    float* dst     = isQ ? out : ((which == 1) ? g_k : g_v);
    const int Kdim = isQ ? KX : KY;
    const int ntile = (isQ ? KX : KY_PAD) >> 4;   // 48 or 18

    float4 pfx[2];   // Q: x prefetch (aligned float4)
    float  pfy[8];   // KV: y prefetch (scalar guarded)
    float  pfw[5];   // W prefetch

    auto load_tile = [&](int t) {
        const int k0 = t << 4;
        if (isQ) {
#pragma unroll
            for (int s = 0; s < 2; s++) {
                const int i = tid + s * 256;
                const int r = i >> 2, q4 = i & 3;
                pfx[s] = *(const float4*)&x[(size_t)(m0 + r) * KX + k0 + q4 * 4];
            }
        } else {
#pragma unroll
            for (int s = 0; s < 8; s++) {
                const int i = tid + s * 256;
                const int r = i >> 4, kk = i & 15;
                const int k = k0 + kk;
                pfy[s] = (k < Kdim) ? y[(size_t)(m0 + r) * KY + k] : 0.0f;
            }
        }
#pragma unroll
        for (int s = 0; s < 5; s++) {
            const int i = tid + s * 256;
            const int kk = i / 80, j = i - kk * 80;
            const int k = k0 + kk;
            pfw[s] = (k < Kdim) ? W[(size_t)k * 80 + j] : 0.0f;
        }
    };
    auto store_tile = [&](int buf) {
        if (isQ) {
#pragma unroll
            for (int s = 0; s < 2; s++) {
                const int i = tid + s * 256;
                const int r = i >> 2, q4 = i & 3;
                const float v[4] = { pfx[s].x, pfx[s].y, pfx[s].z, pfx[s].w };
#pragma unroll
                for (int j = 0; j < 4; j++)
                    sxh[buf * 2176 + (q4 * 4 + j) * 136 + r] = f2tf32(v[j]);
            }
        } else {
#pragma unroll
            for (int s = 0; s < 8; s++) {
                const int i = tid + s * 256;
                const int r = i >> 4, kk = i & 15;
                sxh[buf * 2176 + kk * 136 + r] = f2tf32(pfy[s]);
            }
        }
#pragma unroll
        for (int s = 0; s < 5; s++) {
            const int i = tid + s * 256;
            const int kk = i / 80, j = i - kk * 80;
            swh[buf * 1408 + kk * 88 + j] = f2tf32(pfw[s]);
        }
    };

    float c[10][4];
#pragma unroll
    for (int n = 0; n < 10; n++)
#pragma unroll
        for (int j = 0; j < 4; j++) c[n][j] = 0.0f;

    load_tile(0);
    store_tile(0);
    __syncthreads();

    const int arow = warp * 16 + g;

    for (int t = 0; t < ntile; t++) {
        const int cur = t & 1;
        const bool more = (t + 1 < ntile);
        if (more) load_tile(t + 1);

        const uint32_t* SXH = sxh + cur * 2176;
        const uint32_t* SWH = swh + cur * 1408;

#pragma unroll
        for (int k8 = 0; k8 < 2; k8++) {
            const int kb = k8 * 8;
            uint32_t ah[4];
            ah[0] = SXH[(kb + tig) * 136 + arow];
            ah[1] = SXH[(kb + tig) * 136 + arow + 8];
            ah[2] = SXH[(kb + tig + 4) * 136 + arow];
            ah[3] = SXH[(kb + tig + 4) * 136 + arow + 8];
#pragma unroll
            for (int n = 0; n < 10; n++) {
                const uint32_t b0 = SWH[(kb + tig) * 88 + n * 8 + g];
                const uint32_t b1 = SWH[(kb + tig + 4) * 88 + n * 8 + g];
                mma_tf32(c[n], ah, b0, b1);
            }
        }

        if (more) store_tile((t + 1) & 1);
        __syncthreads();
    }

    float* o0 = &dst[(size_t)(m0 + warp * 16 + g) * DMODEL];
    float* o1 = o0 + (size_t)8 * DMODEL;
#pragma unroll
    for (int n = 0; n < 10; n++) {
        *(float2*)&o0[n * 8 + 2 * tig] = make_float2(c[n][0], c[n][1]);
        *(float2*)&o1[n * 8 + 2 * tig] = make_float2(c[n][2], c[n][3]);
    }
}

// ---------------- Attention v8: tensor FA, shuffle-free (f16 P/V for AV) ----------------
// (unchanged from R15 — 74us, verified)
#define SKSTR 520
#define SVSTR 536                                  // halves per n-row
#define SV_OFF (16 * SKSTR)                        // f32 index where V (half) starts
#define ATTN_SMEM (16 * SKSTR * 4 + 16 * SVSTR * 2)  // 33280 + 17152 = 50432

__global__ void __launch_bounds__(256, 4) attn_kernel(float* __restrict__ qo)
{
    extern __shared__ __align__(16) float fs[];
    float* sk = fs;                                // [16][SKSTR] f32
    uint16_t* svh = (uint16_t*)(fs + SV_OFF);      // [16][SVSTR] f16 bits

    const int b = blockIdx.x >> 3;
    const int h = blockIdx.x & 7;
    const int tid = threadIdx.x;
    const float scale = 0.31622776601683794f * 1.4426950408889634f;  // 1/sqrt(10)*log2e

    // stage K transposed + scaled + tf32
    for (int i = tid; i < NY * DHEAD; i += 256) {
        const int key = i / DHEAD, d = i - key * DHEAD;
        const float v = g_k[(size_t)(b * NY + key) * DMODEL + h * DHEAD + d] * scale;
        sk[d * SKSTR + key] = __uint_as_float(f2tf32(v));
    }
    for (int i = tid; i < 6 * 512; i += 256) {     // zero K pad rows 10..15
        const int r = 10 + (i >> 9), key = i & 511;
        sk[r * SKSTR + key] = 0.0f;
    }
    // stage V transposed f16: svh[n][key]
    for (int i = tid; i < 512 * 16; i += 256) {
        const int key = i >> 4, n = i & 15;
        const float v = (n < DHEAD)
            ? g_v[(size_t)(b * NY + key) * DMODEL + h * DHEAD + n] : 0.0f;
        svh[n * SVSTR + key] = f2h(v);
    }
    __syncthreads();

    const int warp = tid >> 5;
    const int lane = tid & 31;
    const int g    = lane >> 2;      // 0..7
    const int tig  = lane & 3;       // 0..3

    const float* pK0 = sk + tig * SKSTR + g;        // k rows tig / tig+4
    const float* pK1 = sk + (tig + 4) * SKSTR + g;
    const uint16_t* pV = svh + 2 * tig;             // + n*SVSTR + key offsets

#pragma unroll 1
    for (int pass = 0; pass < 4; pass++) {
        const int qrow0 = (pass * 8 + warp) * 16;
        float* qb = qo + (size_t)(b * NX + qrow0) * DMODEL + h * DHEAD;

        // Q A-frags (tf32), k padded to 16 with zeros
        uint32_t qa[2][4];
#pragma unroll
        for (int s = 0; s < 2; s++) {
            const int ka = 8 * s + tig, kc = 8 * s + tig + 4;
            qa[s][0] = (ka < DHEAD) ? f2tf32(qb[g * DMODEL + ka]) : 0u;
            qa[s][1] = (ka < DHEAD) ? f2tf32(qb[(g + 8) * DMODEL + ka]) : 0u;
            qa[s][2] = (kc < DHEAD) ? f2tf32(qb[g * DMODEL + kc]) : 0u;
            qa[s][3] = (kc < DHEAD) ? f2tf32(qb[(g + 8) * DMODEL + kc]) : 0u;
        }

        float av0[4] = {0.f, 0.f, 0.f, 0.f};   // out cols 0..7
        float av1[4] = {0.f, 0.f, 0.f, 0.f};   // out cols 8..15 (8,9 real)
        float rs0 = 0.f, rs1 = 0.f;            // row sums (rows g, g+8)

        for (int ch = 0; ch < 32; ch++) {
            const int key0 = ch * 16;
            float e0[4], e1[4];
            // --- scores: two n8 key tiles -> ex2 ---
#pragma unroll
            for (int t = 0; t < 2; t++) {
                float c[4] = {0.f, 0.f, 0.f, 0.f};
                const int kt = key0 + t * 8;
                mma_tf32(c, qa[0], __float_as_uint(pK0[kt]),
                                   __float_as_uint(pK1[kt]));
                mma_tf32(c, qa[1], __float_as_uint(pK0[8 * SKSTR + kt]),
                                   __float_as_uint(pK1[8 * SKSTR + kt]));
                float* e = t ? e1 : e0;
#pragma unroll
                for (int j = 0; j < 4; j++)
                    asm("ex2.approx.f32 %0, %1;" : "=f"(e[j]) : "f"(c[j]));
                rs0 += e[0] + e[1];
                rs1 += e[2] + e[3];
            }
            // --- P C-frags == f16 A-frags (no shuffle) ---
            uint32_t pa[4];
            pa[0] = f16x2(e0[0], e0[1]);   // A(g,   2tig), A(g,   2tig+1)
            pa[1] = f16x2(e0[2], e0[3]);   // A(g+8, 2tig), A(g+8, 2tig+1)
            pa[2] = f16x2(e1[0], e1[1]);   // A(g,   2tig+8), ...
            pa[3] = f16x2(e1[2], e1[3]);   // A(g+8, 2tig+8), ...
            // --- AV: 2 f16 m16n8k16 MMAs; B-frags from svh[n][key] ---
            {
                const uint16_t* p = pV + g * SVSTR + key0;
                const uint32_t b0 = *(const uint32_t*)(p);      // keys 2tig,2tig+1
                const uint32_t b1 = *(const uint32_t*)(p + 8);  // keys 2tig+8,+9
                mma_f16(av0, pa, b0, b1);
            }
            {
                const uint16_t* p = pV + (8 + g) * SVSTR + key0;
                const uint32_t b0 = *(const uint32_t*)(p);
                const uint32_t b1 = *(const uint32_t*)(p + 8);
                mma_f16(av1, pa, b0, b1);
            }
        }

        // reduce row sums across the quad (cols split over tig)
        rs0 += __shfl_xor_sync(0xffffffffu, rs0, 1);
        rs0 += __shfl_xor_sync(0xffffffffu, rs0, 2);
        rs1 += __shfl_xor_sync(0xffffffffu, rs1, 1);
        rs1 += __shfl_xor_sync(0xffffffffu, rs1, 2);
        const float inv0 = 1.0f / rs0;
        const float inv1 = 1.0f / rs1;

        // out = q + av/rowsum  (rows g, g+8; cols 2tig,2tig+1; tig==0 also 8,9)
        float* o0 = qb + g * DMODEL;
        float* o1 = qb + (g + 8) * DMODEL;
        {
            float2 q0 = *(float2*)&o0[2 * tig];
            float2 q1 = *(float2*)&o1[2 * tig];
            *(float2*)&o0[2 * tig] = make_float2(q0.x + av0[0] * inv0, q0.y + av0[1] * inv0);
            *(float2*)&o1[2 * tig] = make_float2(q1.x + av0[2] * inv1, q1.y + av0[3] * inv1);
        }
        if (tig == 0) {
            float2 q0 = *(float2*)&o0[8];
            float2 q1 = *(float2*)&o1[8];
            *(float2*)&o0[8] = make_float2(q0.x + av1[0] * inv0, q0.y + av1[1] * inv0);
            *(float2*)&o1[8] = make_float2(q1.x + av1[2] * inv1, q1.y + av1[3] * inv1);
        }
    }
}

extern "C" void kernel_launch(void* const* d_in, const int* in_sizes, int n_in,
                              void* d_out, int out_size)
{
    const float* x  = (const float*)d_in[0];
    const float* y  = (const float*)d_in[1];
    const float* Wq = (const float*)d_in[2];
    const float* Wk = (const float*)d_in[3];
    const float* Wv = (const float*)d_in[4];
    float* out = (float*)d_out;

    cudaFuncSetAttribute(proj_mma_kernel, cudaFuncAttributeMaxDynamicSharedMemorySize, PJ_SMEM_BYTES);
    cudaFuncSetAttribute(attn_kernel, cudaFuncAttributeMaxDynamicSharedMemorySize, ATTN_SMEM);

    proj_mma_kernel<<<768, 256, PJ_SMEM_BYTES>>>(x, y, Wq, Wk, Wv, out);
    attn_kernel<<<BATCH * NHEAD, 256, ATTN_SMEM>>>(out);  // out = q + att, in place
}

// round 17
// speedup vs baseline: 4.1231x; 1.0022x over previous
#include <cuda_runtime.h>
#include <cuda_fp16.h>
#include <cstdint>

#define BATCH 64
#define NX    512
#define NY    512
#define NHEAD 8
#define DHEAD 10
#define DMODEL 80     // NHEAD*DHEAD
#define KX    768
#define KY    283
#define KY_PAD 288

// scratch for K/V projections — device globals per harness rules
__device__ float g_k[BATCH * NY * DMODEL];
__device__ float g_v[BATCH * NY * DMODEL];

// ---------------- tf32 / f16 mma helpers (base PTX, works on .target sm_103) ----------------
__device__ __forceinline__ uint32_t f2tf32(float f) {
    uint32_t u; asm("cvt.rna.tf32.f32 %0, %1;" : "=r"(u) : "f"(f)); return u;
}
__device__ __forceinline__ void mma_tf32(float c[4], const uint32_t a[4],
                                         uint32_t b0, uint32_t b1) {
    asm volatile(
        "mma.sync.aligned.m16n8k8.row.col.f32.tf32.tf32.f32 "
        "{%0,%1,%2,%3}, {%4,%5,%6,%7}, {%8,%9}, {%0,%1,%2,%3};"
        : "+f"(c[0]), "+f"(c[1]), "+f"(c[2]), "+f"(c[3])
        : "r"(a[0]), "r"(a[1]), "r"(a[2]), "r"(a[3]), "r"(b0), "r"(b1));
}
__device__ __forceinline__ void mma_f16(float c[4], const uint32_t a[4],
                                        uint32_t b0, uint32_t b1) {
    asm volatile(
        "mma.sync.aligned.m16n8k16.row.col.f32.f16.f16.f32 "
        "{%0,%1,%2,%3}, {%4,%5,%6,%7}, {%8,%9}, {%0,%1,%2,%3};"
        : "+f"(c[0]), "+f"(c[1]), "+f"(c[2]), "+f"(c[3])
        : "r"(a[0]), "r"(a[1]), "r"(a[2]), "r"(a[3]), "r"(b0), "r"(b1));
}
__device__ __forceinline__ uint32_t f16x2(float lo, float hi) {
    uint32_t u;  // cvt d, a(hi), b(lo): lo -> lower half
    asm("cvt.rn.f16x2.f32 %0, %1, %2;" : "=r"(u) : "f"(hi), "f"(lo));
    return u;
}
__device__ __forceinline__ uint16_t f2h(float f) {
    uint16_t h; asm("cvt.rn.f16.f32 %0, %1;" : "=h"(h) : "f"(f)); return h;
}

// ---------------- Projection via mma.sync tf32 (single-term, uniform Q/K/V) ----------------
// 768 CTAs x 256 thr (8 warps): [0,256) Q ; [256,512) K ; [512,768) V.
// Block tile 128 rows x 80 cols; warp tile m16 x n80; K chunk = 16 (2 k8 steps).
// __launch_bounds__(256,3): cap ~85 regs -> 3 blocks/SM (latency-bound fix).
#define SXH_OFF 0
#define SWH_OFF 4352            // 2*16*136
#define PJ_SMEM_U32 7168        // + 2*16*88
#define PJ_SMEM_BYTES (PJ_SMEM_U32 * 4)

__global__ void __launch_bounds__(256, 3) proj_mma_kernel(
    const float* __restrict__ x, const float* __restrict__ y,
    const float* __restrict__ Wq, const float* __restrict__ Wk,
    const float* __restrict__ Wv, float* __restrict__ out)
{
    extern __shared__ __align__(16) uint32_t su[];
    uint32_t* sxh = su + SXH_OFF;
    uint32_t* swh = su + SWH_OFF;

    const int tid   = threadIdx.x;
    const int warp  = tid >> 5;
    const int lane  = tid & 31;
    const int g     = lane >> 2;       // 0..7
    const int tig   = lane & 3;        // 0..3
    const int which = blockIdx.x >> 8; // 0=Q, 1=K, 2=V
    const bool isQ  = (which == 0);
    const int m0    = (blockIdx.x & 255) * 128;

    const float* W = isQ ? Wq : ((which == 1) ? Wk : Wv);
    float* dst     = isQ ? out : ((which == 1) ? g_k : g_v);
    const int Kdim = isQ ? KX : KY;
    const int ntile = (isQ ? KX : KY_PAD) >> 4;   // 48 or 18

    float4 pfx[2];   // Q: x prefetch (aligned float4)
    float  pfy[8];   // KV: y prefetch (scalar guarded)
    float  pfw[5];   // W prefetch

    auto load_tile = [&](int t) {
        const int k0 = t << 4;
        if (isQ) {
#pragma unroll
            for (int s = 0; s < 2; s++) {
                const int i = tid + s * 256;
                const int r = i >> 2, q4 = i & 3;
                pfx[s] = *(const float4*)&x[(size_t)(m0 + r) * KX + k0 + q4 * 4];
            }
        } else {
#pragma unroll
            for (int s = 0; s < 8; s++) {
                const int i = tid + s * 256;
                const int r = i >> 4, kk = i & 15;
                const int k = k0 + kk;
                pfy[s] = (k < Kdim) ? y[(size_t)(m0 + r) * KY + k] : 0.0f;
            }
        }
#pragma unroll
        for (int s = 0; s < 5; s++) {
            const int i = tid + s * 256;
            const int kk = i / 80, j = i - kk * 80;
            const int k = k0 + kk;
            pfw[s] = (k < Kdim) ? W[(size_t)k * 80 + j] : 0.0f;
        }
    };
    auto store_tile = [&](int buf) {
        if (isQ) {
#pragma unroll
            for (int s = 0; s < 2; s++) {
                const int i = tid + s * 256;
                const int r = i >> 2, q4 = i & 3;
                const float v[4] = { pfx[s].x, pfx[s].y, pfx[s].z, pfx[s].w };
#pragma unroll
                for (int j = 0; j < 4; j++)
                    sxh[buf * 2176 + (q4 * 4 + j) * 136 + r] = f2tf32(v[j]);
            }
        } else {
#pragma unroll
            for (int s = 0; s < 8; s++) {
                const int i = tid + s * 256;
                const int r = i >> 4, kk = i & 15;
                sxh[buf * 2176 + kk * 136 + r] = f2tf32(pfy[s]);
            }
        }
#pragma unroll
        for (int s = 0; s < 5; s++) {
            const int i = tid + s * 256;
            const int kk = i / 80, j = i - kk * 80;
            swh[buf * 1408 + kk * 88 + j] = f2tf32(pfw[s]);
        }
    };

    float c[10][4];
#pragma unroll
    for (int n = 0; n < 10; n++)
#pragma unroll
        for (int j = 0; j < 4; j++) c[n][j] = 0.0f;

    load_tile(0);
    store_tile(0);
    __syncthreads();

    const int arow = warp * 16 + g;

    for (int t = 0; t < ntile; t++) {
        const int cur = t & 1;
        const bool more = (t + 1 < ntile);
        if (more) load_tile(t + 1);

        const uint32_t* SXH = sxh + cur * 2176;
        const uint32_t* SWH = swh + cur * 1408;

#pragma unroll
        for (int k8 = 0; k8 < 2; k8++) {
            const int kb = k8 * 8;
            uint32_t ah[4];
            ah[0] = SXH[(kb + tig) * 136 + arow];
            ah[1] = SXH[(kb + tig) * 136 + arow + 8];
            ah[2] = SXH[(kb + tig + 4) * 136 + arow];
            ah[3] = SXH[(kb + tig + 4) * 136 + arow + 8];
#pragma unroll
            for (int n = 0; n < 10; n++) {
                const uint32_t b0 = SWH[(kb + tig) * 88 + n * 8 + g];
                const uint32_t b1 = SWH[(kb + tig + 4) * 88 + n * 8 + g];
                mma_tf32(c[n], ah, b0, b1);
            }
        }

        if (more) store_tile((t + 1) & 1);
        __syncthreads();
    }

    float* o0 = &dst[(size_t)(m0 + warp * 16 + g) * DMODEL];
    float* o1 = o0 + (size_t)8 * DMODEL;
#pragma unroll
    for (int n = 0; n < 10; n++) {
        *(float2*)&o0[n * 8 + 2 * tig] = make_float2(c[n][0], c[n][1]);
        *(float2*)&o1[n * 8 + 2 * tig] = make_float2(c[n][2], c[n][3]);
    }
}

// ---------------- Attention v9: all-f16 tensor FA (f16 scores + f16 AV) ----------------
// One block per (b,h), 8 warps. K stored [key][16] f16 (pre-scaled by
// scale*log2e, cols 10..15 zero; 32B rows -> B-frag loads 2-way conflict, fine).
// V stored [n(16)][key] f16 (stride 536). Per 16-key chunk: 2 f16 score MMAs
// (m16n8k16) -> ex2 on C-frags -> f16x2 pack = A-frag layout (no shuffles)
// -> 2 f16 AV MMAs. Row sums quad-reduced at end. smem 33.5KB, 4 blocks/SM.
#define SVSTR 536                                  // halves per V n-row
#define SVK_HALVES (512 * 16)                      // K region: 16384 halves
#define ATTN_SMEM (SVK_HALVES * 2 + 16 * SVSTR * 2)  // 32768 + 17152 = 49920? no: 16384*2=32768 + 17152 = 49920... wait K is 16KB
// K: 512*16*2 = 16384 B; V: 16*536*2 = 17152 B; total 33536 B
#undef ATTN_SMEM
#define ATTN_SMEM (512 * 16 * 2 + 16 * SVSTR * 2)  // 33536

__global__ void __launch_bounds__(256, 4) attn_kernel(float* __restrict__ qo)
{
    extern __shared__ __align__(16) uint16_t hs[];
    uint16_t* svk = hs;                            // [512][16] f16 (K, pre-scaled)
    uint16_t* svh = hs + 512 * 16;                 // [16][SVSTR] f16 (V transposed)

    const int b = blockIdx.x >> 3;
    const int h = blockIdx.x & 7;
    const int tid = threadIdx.x;
    const float scale = 0.31622776601683794f * 1.4426950408889634f;  // 1/sqrt(10)*log2e

    // stage K [key][16] f16, scaled, cols 10..15 zero
    for (int i = tid; i < 512 * 16; i += 256) {
        const int key = i >> 4, k = i & 15;
        const float v = (k < DHEAD)
            ? g_k[(size_t)(b * NY + key) * DMODEL + h * DHEAD + k] * scale : 0.0f;
        svk[key * 16 + k] = f2h(v);
    }
    // stage V transposed f16: svh[n][key]
    for (int i = tid; i < 512 * 16; i += 256) {
        const int key = i >> 4, n = i & 15;
        const float v = (n < DHEAD)
            ? g_v[(size_t)(b * NY + key) * DMODEL + h * DHEAD + n] : 0.0f;
        svh[n * SVSTR + key] = f2h(v);
    }
    __syncthreads();

    const int warp = tid >> 5;
    const int lane = tid & 31;
    const int g    = lane >> 2;      // 0..7
    const int tig  = lane & 3;       // 0..3

    const uint32_t* pK = (const uint32_t*)svk;      // word view: key*8 + word
    const uint16_t* pV = svh + 2 * tig;             // + n*SVSTR + key offsets

#pragma unroll 1
    for (int pass = 0; pass < 4; pass++) {
        const int qrow0 = (pass * 8 + warp) * 16;
        float* qb = qo + (size_t)(b * NX + qrow0) * DMODEL + h * DHEAD;

        // Q A-frag (f16 m16n8k16): rows g,g+8; k = 2tig,2tig+1 (reg0/1), 2tig+8,+9 (reg2/3)
        uint32_t qa[4];
        qa[0] = f16x2(qb[g * DMODEL + 2 * tig],       qb[g * DMODEL + 2 * tig + 1]);
        qa[1] = f16x2(qb[(g + 8) * DMODEL + 2 * tig], qb[(g + 8) * DMODEL + 2 * tig + 1]);
        qa[2] = (tig == 0) ? f16x2(qb[g * DMODEL + 8],       qb[g * DMODEL + 9])       : 0u;
        qa[3] = (tig == 0) ? f16x2(qb[(g + 8) * DMODEL + 8], qb[(g + 8) * DMODEL + 9]) : 0u;

        float av0[4] = {0.f, 0.f, 0.f, 0.f};   // out cols 0..7
        float av1[4] = {0.f, 0.f, 0.f, 0.f};   // out cols 8..15 (8,9 real)
        float rs0 = 0.f, rs1 = 0.f;            // row sums (rows g, g+8)

#pragma unroll 2
        for (int ch = 0; ch < 32; ch++) {
            const int key0 = ch * 16;
            float e0[4], e1[4];
            // --- scores: 2 f16 m16n8k16 MMAs (keys key0..+7, key0+8..+15) ---
            {
                float c[4] = {0.f, 0.f, 0.f, 0.f};
                const int w = (key0 + g) * 8 + tig;
                mma_f16(c, qa, pK[w], pK[w + 4]);
#pragma unroll
                for (int j = 0; j < 4; j++)
                    asm("ex2.approx.f32 %0, %1;" : "=f"(e0[j]) : "f"(c[j]));
                rs0 += e0[0] + e0[1];
                rs1 += e0[2] + e0[3];
            }
            {
                float c[4] = {0.f, 0.f, 0.f, 0.f};
                const int w = (key0 + 8 + g) * 8 + tig;
                mma_f16(c, qa, pK[w], pK[w + 4]);
#pragma unroll
                for (int j = 0; j < 4; j++)
                    asm("ex2.approx.f32 %0, %1;" : "=f"(e1[j]) : "f"(c[j]));
                rs0 += e1[0] + e1[1];
                rs1 += e1[2] + e1[3];
            }
            // --- P C-frags == f16 A-frags (no shuffle) ---
            uint32_t pa[4];
            pa[0] = f16x2(e0[0], e0[1]);   // A(g,   2tig), A(g,   2tig+1)
            pa[1] = f16x2(e0[2], e0[3]);   // A(g+8, 2tig), A(g+8, 2tig+1)
            pa[2] = f16x2(e1[0], e1[1]);   // A(g,   2tig+8), ...
            pa[3] = f16x2(e1[2], e1[3]);   // A(g+8, 2tig+8), ...
            // --- AV: 2 f16 m16n8k16 MMAs; B-frags from svh[n][key] ---
            {
                const uint16_t* p = pV + g * SVSTR + key0;
                const uint32_t b0 = *(const uint32_t*)(p);      // keys 2tig,2tig+1
                const uint32_t b1 = *(const uint32_t*)(p + 8);  // keys 2tig+8,+9
                mma_f16(av0, pa, b0, b1);
            }
            {
                const uint16_t* p = pV + (8 + g) * SVSTR + key0;
                const uint32_t b0 = *(const uint32_t*)(p);
                const uint32_t b1 = *(const uint32_t*)(p + 8);
                mma_f16(av1, pa, b0, b1);
            }
        }

        // reduce row sums across the quad (cols split over tig)
        rs0 += __shfl_xor_sync(0xffffffffu, rs0, 1);
        rs0 += __shfl_xor_sync(0xffffffffu, rs0, 2);
        rs1 += __shfl_xor_sync(0xffffffffu, rs1, 1);
        rs1 += __shfl_xor_sync(0xffffffffu, rs1, 2);
        const float inv0 = 1.0f / rs0;
        const float inv1 = 1.0f / rs1;

        // out = q + av/rowsum  (rows g, g+8; cols 2tig,2tig+1; tig==0 also 8,9)
        float* o0 = qb + g * DMODEL;
        float* o1 = qb + (g + 8) * DMODEL;
        {
            float2 q0 = *(float2*)&o0[2 * tig];
            float2 q1 = *(float2*)&o1[2 * tig];
            *(float2*)&o0[2 * tig] = make_float2(q0.x + av0[0] * inv0, q0.y + av0[1] * inv0);
            *(float2*)&o1[2 * tig] = make_float2(q1.x + av0[2] * inv1, q1.y + av0[3] * inv1);
        }
        if (tig == 0) {
            float2 q0 = *(float2*)&o0[8];
            float2 q1 = *(float2*)&o1[8];
            *(float2*)&o0[8] = make_float2(q0.x + av1[0] * inv0, q0.y + av1[1] * inv0);
            *(float2*)&o1[8] = make_float2(q1.x + av1[2] * inv1, q1.y + av1[3] * inv1);
        }
    }
}

extern "C" void kernel_launch(void* const* d_in, const int* in_sizes, int n_in,
                              void* d_out, int out_size)
{
    const float* x  = (const float*)d_in[0];
    const float* y  = (const float*)d_in[1];
    const float* Wq = (const float*)d_in[2];
    const float* Wk = (const float*)d_in[3];
    const float* Wv = (const float*)d_in[4];
    float* out = (float*)d_out;

    cudaFuncSetAttribute(proj_mma_kernel, cudaFuncAttributeMaxDynamicSharedMemorySize, PJ_SMEM_BYTES);
    cudaFuncSetAttribute(attn_kernel, cudaFuncAttributeMaxDynamicSharedMemorySize, ATTN_SMEM);

    proj_mma_kernel<<<768, 256, PJ_SMEM_BYTES>>>(x, y, Wq, Wk, Wv, out);
    attn_kernel<<<BATCH * NHEAD, 256, ATTN_SMEM>>>(out);  // out = q + att, in place
}